// round 5
// baseline (speedup 1.0000x reference)
#include <cuda_runtime.h>
#include <math.h>

// Problem constants
#define BB   32
#define LL   400
#define HH   512
#define NHH  8
#define DHH  64
#define KW   7
#define NCC  4
#define MM   (BB * LL)      // 12800 tokens
#define H3   (3 * HH)       // 1536

// ---------------------------------------------------------------------------
// Scratch
// ---------------------------------------------------------------------------
__device__ float g_norm  [MM * HH];
__device__ float g_dwout [MM * HH];
__device__ float g_qkv   [MM * H3];
__device__ float g_attout[MM * HH];
// pre-rounded (tf32) weights: pw | qkv | out | ff
#define WT_PW   0
#define WT_QKV  (NCC * HH * HH)                 // 1048576
#define WT_OUT  (WT_QKV + H3 * HH)              // 1835008
#define WT_FF   (WT_OUT + HH * HH)              // 2097152
#define WT_TOT  (WT_FF + HH * HH)               // 2359296
__device__ float g_wt[WT_TOT];

// ---------------------------------------------------------------------------
// tf32 helpers
// ---------------------------------------------------------------------------
__device__ __forceinline__ unsigned f2tf32(float x) {
    unsigned r;
    asm("cvt.rna.tf32.f32 %0, %1;" : "=r"(r) : "f"(x));
    return r;
}
__device__ __forceinline__ float round_tf32(float x) {
    return __uint_as_float(f2tf32(x));
}

__device__ __forceinline__ void mma_tf32(float* d, const unsigned* a, const unsigned* b) {
    asm volatile(
        "mma.sync.aligned.m16n8k8.row.col.f32.tf32.tf32.f32 "
        "{%0,%1,%2,%3}, {%4,%5,%6,%7}, {%8,%9}, {%0,%1,%2,%3};\n"
        : "+f"(d[0]), "+f"(d[1]), "+f"(d[2]), "+f"(d[3])
        : "r"(a[0]), "r"(a[1]), "r"(a[2]), "r"(a[3]), "r"(b[0]), "r"(b[1]));
}

__device__ __forceinline__ void cp_async16(void* smem_dst, const void* gsrc) {
    unsigned sa = (unsigned)__cvta_generic_to_shared(smem_dst);
    asm volatile("cp.async.cg.shared.global [%0], [%1], 16;\n" :: "r"(sa), "l"(gsrc));
}

// ---------------------------------------------------------------------------
// Pre-round weights to tf32 (idempotent rounding; bit-exact vs cvt-at-read).
// ---------------------------------------------------------------------------
__global__ void round_w_kernel(const float* __restrict__ in, float* __restrict__ out, int n4) {
    int i = blockIdx.x * blockDim.x + threadIdx.x;
    if (i >= n4) return;
    float4 v = ((const float4*)in)[i];
    v.x = round_tf32(v.x); v.y = round_tf32(v.y);
    v.z = round_tf32(v.z); v.w = round_tf32(v.w);
    ((float4*)out)[i] = v;
}

// ---------------------------------------------------------------------------
// out = x + positional encoding
// ---------------------------------------------------------------------------
__global__ void add_pe_kernel(const float* __restrict__ x, float* __restrict__ out) {
    int idx = blockIdx.x * blockDim.x + threadIdx.x;
    if (idx >= MM * HH) return;
    int h = idx & (HH - 1);
    int l = (idx / HH) % LL;
    float freq = expf(-(float)(h & ~1) * (9.210340371976184f / (float)HH));
    float a = (float)l * freq;
    float pe = (h & 1) ? cosf(a) : sinf(a);
    out[idx] = x[idx] + pe;
}

// ---------------------------------------------------------------------------
// LayerNorm. TF32OUT: round output (feeds GEMM A directly, numerics identical
// to cvt-at-read). Non-TF32OUT: full fp32 (feeds dwconv).
// ---------------------------------------------------------------------------
template <bool TF32OUT>
__global__ void ln_kernel(const float* __restrict__ in, float* __restrict__ out,
                          const float* __restrict__ gw, const float* __restrict__ gb) {
    int row = blockIdx.x;
    int t   = threadIdx.x;  // 128
    const float4* p = (const float4*)(in + (size_t)row * HH);
    float4 v = p[t];

    __shared__ float sh[4];

    float s = v.x + v.y + v.z + v.w;
    #pragma unroll
    for (int o = 16; o > 0; o >>= 1) s += __shfl_down_sync(0xffffffffu, s, o);
    if ((t & 31) == 0) sh[t >> 5] = s;
    __syncthreads();
    float mean = (sh[0] + sh[1] + sh[2] + sh[3]) * (1.0f / HH);
    __syncthreads();

    float dx = v.x - mean, dy = v.y - mean, dz = v.z - mean, dw = v.w - mean;
    float q = dx * dx + dy * dy + dz * dz + dw * dw;
    #pragma unroll
    for (int o = 16; o > 0; o >>= 1) q += __shfl_down_sync(0xffffffffu, q, o);
    if ((t & 31) == 0) sh[t >> 5] = q;
    __syncthreads();
    float var  = (sh[0] + sh[1] + sh[2] + sh[3]) * (1.0f / HH);
    float rstd = rsqrtf(var + 1e-5f);

    float4 g4 = ((const float4*)gw)[t];
    float4 b4 = ((const float4*)gb)[t];
    float4 o4;
    o4.x = dx * rstd * g4.x + b4.x;
    o4.y = dy * rstd * g4.y + b4.y;
    o4.z = dz * rstd * g4.z + b4.z;
    o4.w = dw * rstd * g4.w + b4.w;
    if (TF32OUT) {
        o4.x = round_tf32(o4.x); o4.y = round_tf32(o4.y);
        o4.z = round_tf32(o4.z); o4.w = round_tf32(o4.w);
    }
    ((float4*)(out + (size_t)row * HH))[t] = o4;
}

// ---------------------------------------------------------------------------
// Depthwise conv K=7, pad 3. fp32 math, tf32-rounded output (feeds GEMM A).
// ---------------------------------------------------------------------------
__global__ void dwconv_kernel(const float* __restrict__ norm, float* __restrict__ outb,
                              const float* __restrict__ w, const float* __restrict__ bias) {
    int idx = blockIdx.x * blockDim.x + threadIdx.x;
    if (idx >= MM * HH) return;
    int c = idx & (HH - 1);
    int l = (idx / HH) % LL;
    int b = idx / (HH * LL);
    const float* wr = w + c * KW;
    float acc = bias[c];
    #pragma unroll
    for (int k = 0; k < KW; k++) {
        int ll = l + k - 3;
        if (ll >= 0 && ll < LL)
            acc += norm[((size_t)b * LL + ll) * HH + c] * wr[k];
    }
    outb[idx] = round_tf32(acc);
}

// ---------------------------------------------------------------------------
// tf32 tensor-core GEMM, double-buffered cp.async, NO inner-loop cvt
// (A and W are pre-rounded tf32 bit patterns).
// BM=128, BN=128, BK=16, 256 threads (8 warps, 2x4), warp tile 64x32.
// TF32OUT rounds C (when C feeds another GEMM/flash as A-operand).
// ---------------------------------------------------------------------------
template <bool RELU, bool RES, bool TF32OUT>
__global__ void __launch_bounds__(256, 2)
gemm_tf32_kernel(const float* __restrict__ A, const float* __restrict__ W,
                 const float* __restrict__ bias, const float* __restrict__ R,
                 float* __restrict__ C, int Md, int Nd, int Kd) {
    __shared__ float As[2][128][20];
    __shared__ float Bs[2][128][20];

    int tid  = threadIdx.x;
    int m0   = blockIdx.y * 128;
    int n0   = blockIdx.x * 128;
    int warp = tid >> 5;
    int lane = tid & 31;
    int wm   = (warp >> 2) * 64;
    int wn   = (warp & 3) * 32;
    int lg   = lane >> 2;
    int lq   = lane & 3;

    int lrow = tid >> 2;
    int lk   = (tid & 3) * 4;

    const float* Ar0 = &A[(size_t)(m0 + lrow)      * Kd + lk];
    const float* Ar1 = &A[(size_t)(m0 + 64 + lrow) * Kd + lk];
    const float* Wr0 = &W[(size_t)(n0 + lrow)      * Kd + lk];
    const float* Wr1 = &W[(size_t)(n0 + 64 + lrow) * Kd + lk];

    float acc[4][4][4];
    #pragma unroll
    for (int i = 0; i < 4; i++)
        #pragma unroll
        for (int j = 0; j < 4; j++)
            #pragma unroll
            for (int r = 0; r < 4; r++) acc[i][j][r] = 0.0f;

    cp_async16(&As[0][lrow][lk],      Ar0);
    cp_async16(&As[0][64 + lrow][lk], Ar1);
    cp_async16(&Bs[0][lrow][lk],      Wr0);
    cp_async16(&Bs[0][64 + lrow][lk], Wr1);
    asm volatile("cp.async.commit_group;\n");

    int nit = Kd >> 4;
    for (int it = 0; it < nit; it++) {
        int cur = it & 1;
        if (it + 1 < nit) {
            int nxt = cur ^ 1;
            int ko  = (it + 1) << 4;
            cp_async16(&As[nxt][lrow][lk],      Ar0 + ko);
            cp_async16(&As[nxt][64 + lrow][lk], Ar1 + ko);
            cp_async16(&Bs[nxt][lrow][lk],      Wr0 + ko);
            cp_async16(&Bs[nxt][64 + lrow][lk], Wr1 + ko);
            asm volatile("cp.async.commit_group;\n");
            asm volatile("cp.async.wait_group 1;\n");
        } else {
            asm volatile("cp.async.wait_group 0;\n");
        }
        __syncthreads();

        #pragma unroll
        for (int ks = 0; ks < 2; ks++) {
            int kb = ks * 8;
            unsigned af[4][4], bf[4][2];
            #pragma unroll
            for (int mt = 0; mt < 4; mt++) {
                int mr = wm + mt * 16 + lg;
                af[mt][0] = __float_as_uint(As[cur][mr][kb + lq]);
                af[mt][1] = __float_as_uint(As[cur][mr + 8][kb + lq]);
                af[mt][2] = __float_as_uint(As[cur][mr][kb + lq + 4]);
                af[mt][3] = __float_as_uint(As[cur][mr + 8][kb + lq + 4]);
            }
            #pragma unroll
            for (int nt = 0; nt < 4; nt++) {
                int nr = wn + nt * 8 + lg;
                bf[nt][0] = __float_as_uint(Bs[cur][nr][kb + lq]);
                bf[nt][1] = __float_as_uint(Bs[cur][nr][kb + lq + 4]);
            }
            #pragma unroll
            for (int mt = 0; mt < 4; mt++)
                #pragma unroll
                for (int nt = 0; nt < 4; nt++)
                    mma_tf32(acc[mt][nt], af[mt], bf[nt]);
        }
        __syncthreads();
    }

    #pragma unroll
    for (int mt = 0; mt < 4; mt++) {
        #pragma unroll
        for (int half = 0; half < 2; half++) {
            int m = m0 + wm + mt * 16 + lg + half * 8;
            #pragma unroll
            for (int nt = 0; nt < 4; nt++) {
                int n = n0 + wn + nt * 8 + 2 * lq;
                float v0 = acc[mt][nt][half * 2 + 0] + bias[n];
                float v1 = acc[mt][nt][half * 2 + 1] + bias[n + 1];
                if (RELU) { v0 = fmaxf(v0, 0.0f); v1 = fmaxf(v1, 0.0f); }
                if (RES)  { v0 += R[(size_t)m * Nd + n]; v1 += R[(size_t)m * Nd + n + 1]; }
                if (TF32OUT) { v0 = round_tf32(v0); v1 = round_tf32(v1); }
                *(float2*)&C[(size_t)m * Nd + n] = make_float2(v0, v1);
            }
        }
    }
}

// ---------------------------------------------------------------------------
// Fused flash attention. qkv is pre-rounded tf32 -> no cvt at load
// (Q scale 0.125 is a power of two: exact on tf32 values).
// ---------------------------------------------------------------------------
#define QS_STRIDE 68
#define VS_STRIDE 72
#define FLASH_SMEM ((64 * QS_STRIDE * 2 + 64 * VS_STRIDE) * 4)

__global__ void __launch_bounds__(128)
flash_kernel(const float* __restrict__ qkv, const int* __restrict__ mask,
             float* __restrict__ attout) {
    extern __shared__ unsigned fsm[];
    unsigned* Qs  = fsm;
    unsigned* KPs = fsm + 64 * QS_STRIDE;
    unsigned* Vs  = fsm + 2 * 64 * QS_STRIDE;
    __shared__ int msk[64];

    int bh = blockIdx.x;
    int b  = bh >> 3;
    int h  = bh & 7;
    int q0 = blockIdx.y * 64;

    int tid  = threadIdx.x;
    int warp = tid >> 5;
    int lane = tid & 31;
    int wr   = warp * 16;
    int lg   = lane >> 2;
    int lq   = lane & 3;

    for (int i = tid; i < 64 * 16; i += 128) {
        int r  = i >> 4;
        int c4 = (i & 15) * 4;
        int qr = q0 + r; if (qr > LL - 1) qr = LL - 1;
        float4 v = *(const float4*)&qkv[((size_t)(b * LL + qr)) * H3 + h * DHH + c4];
        Qs[r * QS_STRIDE + c4 + 0] = __float_as_uint(v.x * 0.125f);
        Qs[r * QS_STRIDE + c4 + 1] = __float_as_uint(v.y * 0.125f);
        Qs[r * QS_STRIDE + c4 + 2] = __float_as_uint(v.z * 0.125f);
        Qs[r * QS_STRIDE + c4 + 3] = __float_as_uint(v.w * 0.125f);
    }

    float oacc[8][4];
    #pragma unroll
    for (int nt = 0; nt < 8; nt++)
        #pragma unroll
        for (int r = 0; r < 4; r++) oacc[nt][r] = 0.0f;
    float m0 = -1e30f, m1 = -1e30f, l0 = 0.0f, l1 = 0.0f;

    for (int kt = 0; kt < LL; kt += 64) {
        __syncthreads();

        for (int i = tid; i < 64 * 16; i += 128) {
            int r  = i >> 4;
            int c4 = (i & 15) * 4;
            int kr = kt + r; if (kr > LL - 1) kr = LL - 1;
            const float* base = &qkv[((size_t)(b * LL + kr)) * H3 + h * DHH + c4];
            float4 kv = *(const float4*)(base + HH);
            float4 vv = *(const float4*)(base + 2 * HH);
            KPs[r * QS_STRIDE + c4 + 0] = __float_as_uint(kv.x);
            KPs[r * QS_STRIDE + c4 + 1] = __float_as_uint(kv.y);
            KPs[r * QS_STRIDE + c4 + 2] = __float_as_uint(kv.z);
            KPs[r * QS_STRIDE + c4 + 3] = __float_as_uint(kv.w);
            Vs[r * VS_STRIDE + c4 + 0] = __float_as_uint(vv.x);
            Vs[r * VS_STRIDE + c4 + 1] = __float_as_uint(vv.y);
            Vs[r * VS_STRIDE + c4 + 2] = __float_as_uint(vv.z);
            Vs[r * VS_STRIDE + c4 + 3] = __float_as_uint(vv.w);
        }
        if (tid < 64) msk[tid] = (kt + tid < LL) ? mask[b * LL + kt + tid] : 0;
        __syncthreads();

        float sacc[8][4];
        #pragma unroll
        for (int nt = 0; nt < 8; nt++)
            #pragma unroll
            for (int r = 0; r < 4; r++) sacc[nt][r] = 0.0f;

        #pragma unroll
        for (int ks = 0; ks < 8; ks++) {
            int kb = ks * 8;
            unsigned af[4];
            af[0] = Qs[(wr + lg)     * QS_STRIDE + kb + lq];
            af[1] = Qs[(wr + lg + 8) * QS_STRIDE + kb + lq];
            af[2] = Qs[(wr + lg)     * QS_STRIDE + kb + lq + 4];
            af[3] = Qs[(wr + lg + 8) * QS_STRIDE + kb + lq + 4];
            #pragma unroll
            for (int nt = 0; nt < 8; nt++) {
                unsigned bf[2];
                bf[0] = KPs[(nt * 8 + lg) * QS_STRIDE + kb + lq];
                bf[1] = KPs[(nt * 8 + lg) * QS_STRIDE + kb + lq + 4];
                mma_tf32(sacc[nt], af, bf);
            }
        }

        float rmax0 = -1e30f, rmax1 = -1e30f;
        #pragma unroll
        for (int nt = 0; nt < 8; nt++) {
            #pragma unroll
            for (int j = 0; j < 2; j++) {
                int kl = nt * 8 + 2 * lq + j;
                bool ok = (kt + kl < LL) && (msk[kl] > 0);
                if (!ok) { sacc[nt][j] = -1e30f; sacc[nt][2 + j] = -1e30f; }
                rmax0 = fmaxf(rmax0, sacc[nt][j]);
                rmax1 = fmaxf(rmax1, sacc[nt][2 + j]);
            }
        }
        #pragma unroll
        for (int o = 1; o <= 2; o <<= 1) {
            rmax0 = fmaxf(rmax0, __shfl_xor_sync(0xffffffffu, rmax0, o));
            rmax1 = fmaxf(rmax1, __shfl_xor_sync(0xffffffffu, rmax1, o));
        }

        float m0n = fmaxf(m0, rmax0);
        float m1n = fmaxf(m1, rmax1);
        float alpha0 = __expf(m0 - m0n);
        float alpha1 = __expf(m1 - m1n);
        m0 = m0n; m1 = m1n;

        float rs0 = 0.0f, rs1 = 0.0f;
        #pragma unroll
        for (int nt = 0; nt < 8; nt++) {
            #pragma unroll
            for (int j = 0; j < 2; j++) {
                float p0 = __expf(sacc[nt][j] - m0);
                float p1 = __expf(sacc[nt][2 + j] - m1);
                sacc[nt][j] = p0;     rs0 += p0;
                sacc[nt][2 + j] = p1; rs1 += p1;
            }
        }
        #pragma unroll
        for (int o = 1; o <= 2; o <<= 1) {
            rs0 += __shfl_xor_sync(0xffffffffu, rs0, o);
            rs1 += __shfl_xor_sync(0xffffffffu, rs1, o);
        }
        l0 = l0 * alpha0 + rs0;
        l1 = l1 * alpha1 + rs1;

        #pragma unroll
        for (int nt = 0; nt < 8; nt++) {
            oacc[nt][0] *= alpha0; oacc[nt][1] *= alpha0;
            oacc[nt][2] *= alpha1; oacc[nt][3] *= alpha1;
        }

        __syncthreads();

        #pragma unroll
        for (int nt = 0; nt < 8; nt++) {
            int c = nt * 8 + 2 * lq;
            KPs[(wr + lg)     * QS_STRIDE + c]     = f2tf32(sacc[nt][0]);
            KPs[(wr + lg)     * QS_STRIDE + c + 1] = f2tf32(sacc[nt][1]);
            KPs[(wr + lg + 8) * QS_STRIDE + c]     = f2tf32(sacc[nt][2]);
            KPs[(wr + lg + 8) * QS_STRIDE + c + 1] = f2tf32(sacc[nt][3]);
        }
        __syncwarp();

        #pragma unroll
        for (int ks = 0; ks < 8; ks++) {
            int kb = ks * 8;
            unsigned af[4];
            af[0] = KPs[(wr + lg)     * QS_STRIDE + kb + lq];
            af[1] = KPs[(wr + lg + 8) * QS_STRIDE + kb + lq];
            af[2] = KPs[(wr + lg)     * QS_STRIDE + kb + lq + 4];
            af[3] = KPs[(wr + lg + 8) * QS_STRIDE + kb + lq + 4];
            #pragma unroll
            for (int nt = 0; nt < 8; nt++) {
                unsigned bf[2];
                bf[0] = Vs[(kb + lq)     * VS_STRIDE + nt * 8 + lg];
                bf[1] = Vs[(kb + lq + 4) * VS_STRIDE + nt * 8 + lg];
                mma_tf32(oacc[nt], af, bf);
            }
        }
    }

    float inv0 = 1.0f / fmaxf(l0, 1e-30f);
    float inv1 = 1.0f / fmaxf(l1, 1e-30f);
    int r0 = q0 + wr + lg;
    int r1 = r0 + 8;
    #pragma unroll
    for (int nt = 0; nt < 8; nt++) {
        int c = nt * 8 + 2 * lq;
        if (r0 < LL)
            *(float2*)&attout[((size_t)(b * LL + r0)) * HH + h * DHH + c] =
                make_float2(round_tf32(oacc[nt][0] * inv0), round_tf32(oacc[nt][1] * inv0));
        if (r1 < LL)
            *(float2*)&attout[((size_t)(b * LL + r1)) * HH + h * DHH + c] =
                make_float2(round_tf32(oacc[nt][2] * inv1), round_tf32(oacc[nt][3] * inv1));
    }
}

// ---------------------------------------------------------------------------
// Launch
// ---------------------------------------------------------------------------
extern "C" void kernel_launch(void* const* d_in, const int* in_sizes, int n_in,
                              void* d_out, int out_size) {
    const float* x         = (const float*)d_in[0];
    const int*   mask      = (const int*)  d_in[1];
    const float* conv_ln_g = (const float*)d_in[2];
    const float* conv_ln_b = (const float*)d_in[3];
    const float* dw_w      = (const float*)d_in[4];
    const float* dw_b      = (const float*)d_in[5];
    const float* pw_w      = (const float*)d_in[6];
    const float* pw_b      = (const float*)d_in[7];
    const float* att_ln_g  = (const float*)d_in[8];
    const float* att_ln_b  = (const float*)d_in[9];
    const float* qkv_w     = (const float*)d_in[10];
    const float* qkv_b     = (const float*)d_in[11];
    const float* out_w     = (const float*)d_in[12];
    const float* out_b     = (const float*)d_in[13];
    const float* ff_ln_g   = (const float*)d_in[14];
    const float* ff_ln_b   = (const float*)d_in[15];
    const float* ff_w      = (const float*)d_in[16];
    const float* ff_b      = (const float*)d_in[17];
    float* out = (float*)d_out;

    float *norm, *dwout, *qkv, *attout, *wt;
    cudaGetSymbolAddress((void**)&norm,   g_norm);
    cudaGetSymbolAddress((void**)&dwout,  g_dwout);
    cudaGetSymbolAddress((void**)&qkv,    g_qkv);
    cudaGetSymbolAddress((void**)&attout, g_attout);
    cudaGetSymbolAddress((void**)&wt,     g_wt);

    cudaFuncSetAttribute(flash_kernel,
                         cudaFuncAttributeMaxDynamicSharedMemorySize, FLASH_SMEM);

    const int elems = MM * HH;

    // Pre-round all GEMM weights to tf32 (bit-exact vs per-read cvt)
    round_w_kernel<<<(WT_QKV / 4 + 255) / 256, 256>>>(pw_w, wt + WT_PW, WT_QKV / 4);
    round_w_kernel<<<(H3 * HH / 4 + 255) / 256, 256>>>(qkv_w, wt + WT_QKV, H3 * HH / 4);
    round_w_kernel<<<(HH * HH / 4 + 255) / 256, 256>>>(out_w, wt + WT_OUT, HH * HH / 4);
    round_w_kernel<<<(HH * HH / 4 + 255) / 256, 256>>>(ff_w, wt + WT_FF, HH * HH / 4);

    add_pe_kernel<<<(elems + 255) / 256, 256>>>(x, out);

    for (int i = 0; i < NCC; i++) {
        ln_kernel<false><<<MM, 128>>>(out, norm, conv_ln_g + i * HH, conv_ln_b + i * HH);
        dwconv_kernel<<<(elems + 255) / 256, 256>>>(norm, dwout,
                                                    dw_w + i * HH * KW, dw_b + i * HH);
        gemm_tf32_kernel<true, true, false><<<dim3(HH / 128, MM / 128), 256>>>(
            dwout, wt + WT_PW + (size_t)i * HH * HH, pw_b + i * HH, out, out, MM, HH, HH);
    }

    ln_kernel<true><<<MM, 128>>>(out, norm, att_ln_g, att_ln_b);
    gemm_tf32_kernel<false, false, true><<<dim3(H3 / 128, MM / 128), 256>>>(
        norm, wt + WT_QKV, qkv_b, nullptr, qkv, MM, H3, HH);

    flash_kernel<<<dim3(BB * NHH, (LL + 63) / 64), 128, FLASH_SMEM>>>(qkv, mask, attout);

    gemm_tf32_kernel<false, true, false><<<dim3(HH / 128, MM / 128), 256>>>(
        attout, wt + WT_OUT, out_b, out, out, MM, HH, HH);

    ln_kernel<true><<<MM, 128>>>(out, norm, ff_ln_g, ff_ln_b);
    gemm_tf32_kernel<true, true, false><<<dim3(HH / 128, MM / 128), 256>>>(
        norm, wt + WT_FF, ff_b, out, out, MM, HH, HH);
}

// round 6
// speedup vs baseline: 1.0494x; 1.0494x over previous
#include <cuda_runtime.h>
#include <math.h>

// Problem constants
#define BB   32
#define LL   400
#define HH   512
#define NHH  8
#define DHH  64
#define KW   7
#define NCC  4
#define MM   (BB * LL)      // 12800 tokens
#define H3   (3 * HH)       // 1536

// ---------------------------------------------------------------------------
// Scratch
// ---------------------------------------------------------------------------
__device__ float g_norm  [MM * HH];
__device__ float g_dwout [MM * HH];
__device__ float g_qkv   [MM * H3];
__device__ float g_attout[MM * HH];
// pre-rounded (tf32) weights: pw | qkv | out | ff
#define WT_PW   0
#define WT_QKV  (NCC * HH * HH)                 // 1048576
#define WT_OUT  (WT_QKV + H3 * HH)              // 1835008
#define WT_FF   (WT_OUT + HH * HH)              // 2097152
#define WT_TOT  (WT_FF + HH * HH)               // 2359296
__device__ float g_wt[WT_TOT];

// ---------------------------------------------------------------------------
// tf32 helpers
// ---------------------------------------------------------------------------
__device__ __forceinline__ unsigned f2tf32(float x) {
    unsigned r;
    asm("cvt.rna.tf32.f32 %0, %1;" : "=r"(r) : "f"(x));
    return r;
}
__device__ __forceinline__ float round_tf32(float x) {
    return __uint_as_float(f2tf32(x));
}

__device__ __forceinline__ void mma_tf32(float* d, const unsigned* a, const unsigned* b) {
    asm volatile(
        "mma.sync.aligned.m16n8k8.row.col.f32.tf32.tf32.f32 "
        "{%0,%1,%2,%3}, {%4,%5,%6,%7}, {%8,%9}, {%0,%1,%2,%3};\n"
        : "+f"(d[0]), "+f"(d[1]), "+f"(d[2]), "+f"(d[3])
        : "r"(a[0]), "r"(a[1]), "r"(a[2]), "r"(a[3]), "r"(b[0]), "r"(b[1]));
}

__device__ __forceinline__ void cp_async16(void* smem_dst, const void* gsrc) {
    unsigned sa = (unsigned)__cvta_generic_to_shared(smem_dst);
    asm volatile("cp.async.cg.shared.global [%0], [%1], 16;\n" :: "r"(sa), "l"(gsrc));
}

// ---------------------------------------------------------------------------
// Merged weight pre-round (one launch for all four weight tensors).
// ---------------------------------------------------------------------------
__global__ void round_all_w_kernel(const float* __restrict__ pw,
                                   const float* __restrict__ qkvw,
                                   const float* __restrict__ ow,
                                   const float* __restrict__ ffw,
                                   float* __restrict__ out) {
    int i = blockIdx.x * blockDim.x + threadIdx.x;       // float4 index
    const int n_pw  = WT_QKV / 4;
    const int n_qkv = (WT_OUT - WT_QKV) / 4;
    const int n_o   = (WT_FF - WT_OUT) / 4;
    const int n_tot = WT_TOT / 4;
    if (i >= n_tot) return;
    const float* src; int off;
    if (i < n_pw)                     { src = pw;   off = i; }
    else if (i < n_pw + n_qkv)        { src = qkvw; off = i - n_pw; }
    else if (i < n_pw + n_qkv + n_o)  { src = ow;   off = i - n_pw - n_qkv; }
    else                              { src = ffw;  off = i - n_pw - n_qkv - n_o; }
    float4 v = ((const float4*)src)[off];
    v.x = round_tf32(v.x); v.y = round_tf32(v.y);
    v.z = round_tf32(v.z); v.w = round_tf32(v.w);
    ((float4*)out)[i] = v;
}

// ---------------------------------------------------------------------------
// out = x + positional encoding
// ---------------------------------------------------------------------------
__global__ void add_pe_kernel(const float* __restrict__ x, float* __restrict__ out) {
    int idx = blockIdx.x * blockDim.x + threadIdx.x;
    if (idx >= MM * HH) return;
    int h = idx & (HH - 1);
    int l = (idx / HH) % LL;
    float freq = expf(-(float)(h & ~1) * (9.210340371976184f / (float)HH));
    float a = (float)l * freq;
    float pe = (h & 1) ? cosf(a) : sinf(a);
    out[idx] = x[idx] + pe;
}

// ---------------------------------------------------------------------------
// LayerNorm. TF32OUT rounds the output (feeds GEMM A; bit-exact vs cvt-at-read).
// ---------------------------------------------------------------------------
template <bool TF32OUT>
__global__ void ln_kernel(const float* __restrict__ in, float* __restrict__ out,
                          const float* __restrict__ gw, const float* __restrict__ gb) {
    int row = blockIdx.x;
    int t   = threadIdx.x;  // 128
    const float4* p = (const float4*)(in + (size_t)row * HH);
    float4 v = p[t];

    __shared__ float sh[4];

    float s = v.x + v.y + v.z + v.w;
    #pragma unroll
    for (int o = 16; o > 0; o >>= 1) s += __shfl_down_sync(0xffffffffu, s, o);
    if ((t & 31) == 0) sh[t >> 5] = s;
    __syncthreads();
    float mean = (sh[0] + sh[1] + sh[2] + sh[3]) * (1.0f / HH);
    __syncthreads();

    float dx = v.x - mean, dy = v.y - mean, dz = v.z - mean, dw = v.w - mean;
    float q = dx * dx + dy * dy + dz * dz + dw * dw;
    #pragma unroll
    for (int o = 16; o > 0; o >>= 1) q += __shfl_down_sync(0xffffffffu, q, o);
    if ((t & 31) == 0) sh[t >> 5] = q;
    __syncthreads();
    float var  = (sh[0] + sh[1] + sh[2] + sh[3]) * (1.0f / HH);
    float rstd = rsqrtf(var + 1e-5f);

    float4 g4 = ((const float4*)gw)[t];
    float4 b4 = ((const float4*)gb)[t];
    float4 o4;
    o4.x = dx * rstd * g4.x + b4.x;
    o4.y = dy * rstd * g4.y + b4.y;
    o4.z = dz * rstd * g4.z + b4.z;
    o4.w = dw * rstd * g4.w + b4.w;
    if (TF32OUT) {
        o4.x = round_tf32(o4.x); o4.y = round_tf32(o4.y);
        o4.z = round_tf32(o4.z); o4.w = round_tf32(o4.w);
    }
    ((float4*)(out + (size_t)row * HH))[t] = o4;
}

// ---------------------------------------------------------------------------
// Depthwise conv K=7, pad 3. fp32 math, tf32-rounded output (feeds GEMM A).
// ---------------------------------------------------------------------------
__global__ void dwconv_kernel(const float* __restrict__ norm, float* __restrict__ outb,
                              const float* __restrict__ w, const float* __restrict__ bias) {
    int idx = blockIdx.x * blockDim.x + threadIdx.x;
    if (idx >= MM * HH) return;
    int c = idx & (HH - 1);
    int l = (idx / HH) % LL;
    int b = idx / (HH * LL);
    const float* wr = w + c * KW;
    float acc = bias[c];
    #pragma unroll
    for (int k = 0; k < KW; k++) {
        int ll = l + k - 3;
        if (ll >= 0 && ll < LL)
            acc += norm[((size_t)b * LL + ll) * HH + c] * wr[k];
    }
    outb[idx] = round_tf32(acc);
}

// ---------------------------------------------------------------------------
// tf32 tensor-core GEMM: BM=128, BN=128, BK=32, double-buffered cp.async with
// ONE __syncthreads per k-iteration. A/W pre-rounded tf32 -> no inner cvt.
// 256 threads (8 warps, 2x4), warp tile 64x32. Dynamic smem 72KB.
// ---------------------------------------------------------------------------
#define GEMM_SS    (128 * 36)                  // floats per stage per array
#define GEMM_SMEM  (2 * GEMM_SS * 2 * 4)       // 73728 bytes

template <bool RELU, bool RES, bool TF32OUT>
__global__ void __launch_bounds__(256, 2)
gemm_tf32_kernel(const float* __restrict__ A, const float* __restrict__ W,
                 const float* __restrict__ bias, const float* __restrict__ R,
                 float* __restrict__ C, int Md, int Nd, int Kd) {
    extern __shared__ float gsm[];
    float* Asm = gsm;                 // [2][128][36]
    float* Bsm = gsm + 2 * GEMM_SS;   // [2][128][36]

    int tid  = threadIdx.x;
    int m0   = blockIdx.y * 128;
    int n0   = blockIdx.x * 128;
    int warp = tid >> 5;
    int lane = tid & 31;
    int wm   = (warp >> 2) * 64;
    int wn   = (warp & 3) * 32;
    int lg   = lane >> 2;
    int lq   = lane & 3;

    int lrow = tid >> 2;          // 0..63
    int lc   = (tid & 3) * 8;     // k offset: 0,8,16,24 (+4 for 2nd cp)

    const float* Ag0 = &A[(size_t)(m0 + lrow)      * Kd + lc];
    const float* Ag1 = &A[(size_t)(m0 + 64 + lrow) * Kd + lc];
    const float* Wg0 = &W[(size_t)(n0 + lrow)      * Kd + lc];
    const float* Wg1 = &W[(size_t)(n0 + 64 + lrow) * Kd + lc];

    float acc[4][4][4];
    #pragma unroll
    for (int i = 0; i < 4; i++)
        #pragma unroll
        for (int j = 0; j < 4; j++)
            #pragma unroll
            for (int r = 0; r < 4; r++) acc[i][j][r] = 0.0f;

    // per-thread smem destinations (stage-relative)
    float* a_d0 = Asm + lrow * 36 + lc;
    float* a_d1 = Asm + (64 + lrow) * 36 + lc;
    float* b_d0 = Bsm + lrow * 36 + lc;
    float* b_d1 = Bsm + (64 + lrow) * 36 + lc;

    #define LOAD_STAGE(s, ko)                                                   \
    {                                                                           \
        int so = (s) * GEMM_SS;                                                 \
        cp_async16(a_d0 + so,     Ag0 + (ko));                                  \
        cp_async16(a_d0 + so + 4, Ag0 + (ko) + 4);                              \
        cp_async16(a_d1 + so,     Ag1 + (ko));                                  \
        cp_async16(a_d1 + so + 4, Ag1 + (ko) + 4);                              \
        cp_async16(b_d0 + so,     Wg0 + (ko));                                  \
        cp_async16(b_d0 + so + 4, Wg0 + (ko) + 4);                              \
        cp_async16(b_d1 + so,     Wg1 + (ko));                                  \
        cp_async16(b_d1 + so + 4, Wg1 + (ko) + 4);                              \
        asm volatile("cp.async.commit_group;\n");                               \
    }

    LOAD_STAGE(0, 0);

    int nit = Kd >> 5;   // BK=32
    for (int it = 0; it < nit; it++) {
        asm volatile("cp.async.wait_group 0;\n");
        __syncthreads();
        if (it + 1 < nit) LOAD_STAGE((it + 1) & 1, (it + 1) << 5);

        int cur = it & 1;
        const float* Asc = Asm + cur * GEMM_SS;
        const float* Bsc = Bsm + cur * GEMM_SS;

        #pragma unroll
        for (int ks = 0; ks < 4; ks++) {
            int kb = ks * 8;
            unsigned af[4][4], bf[4][2];
            #pragma unroll
            for (int mt = 0; mt < 4; mt++) {
                int mr = wm + mt * 16 + lg;
                af[mt][0] = __float_as_uint(Asc[mr * 36 + kb + lq]);
                af[mt][1] = __float_as_uint(Asc[(mr + 8) * 36 + kb + lq]);
                af[mt][2] = __float_as_uint(Asc[mr * 36 + kb + lq + 4]);
                af[mt][3] = __float_as_uint(Asc[(mr + 8) * 36 + kb + lq + 4]);
            }
            #pragma unroll
            for (int nt = 0; nt < 4; nt++) {
                int nr = wn + nt * 8 + lg;
                bf[nt][0] = __float_as_uint(Bsc[nr * 36 + kb + lq]);
                bf[nt][1] = __float_as_uint(Bsc[nr * 36 + kb + lq + 4]);
            }
            #pragma unroll
            for (int mt = 0; mt < 4; mt++)
                #pragma unroll
                for (int nt = 0; nt < 4; nt++)
                    mma_tf32(acc[mt][nt], af[mt], bf[nt]);
        }
    }
    #undef LOAD_STAGE

    #pragma unroll
    for (int mt = 0; mt < 4; mt++) {
        #pragma unroll
        for (int half = 0; half < 2; half++) {
            int m = m0 + wm + mt * 16 + lg + half * 8;
            #pragma unroll
            for (int nt = 0; nt < 4; nt++) {
                int n = n0 + wn + nt * 8 + 2 * lq;
                float v0 = acc[mt][nt][half * 2 + 0] + bias[n];
                float v1 = acc[mt][nt][half * 2 + 1] + bias[n + 1];
                if (RELU) { v0 = fmaxf(v0, 0.0f); v1 = fmaxf(v1, 0.0f); }
                if (RES)  { v0 += R[(size_t)m * Nd + n]; v1 += R[(size_t)m * Nd + n + 1]; }
                if (TF32OUT) { v0 = round_tf32(v0); v1 = round_tf32(v1); }
                *(float2*)&C[(size_t)m * Nd + n] = make_float2(v0, v1);
            }
        }
    }
}

// ---------------------------------------------------------------------------
// Fused flash attention (tf32 MMA, online softmax). qkv pre-rounded tf32.
// ---------------------------------------------------------------------------
#define QS_STRIDE 68
#define VS_STRIDE 72
#define FLASH_SMEM ((64 * QS_STRIDE * 2 + 64 * VS_STRIDE) * 4)

__global__ void __launch_bounds__(128)
flash_kernel(const float* __restrict__ qkv, const int* __restrict__ mask,
             float* __restrict__ attout) {
    extern __shared__ unsigned fsm[];
    unsigned* Qs  = fsm;
    unsigned* KPs = fsm + 64 * QS_STRIDE;
    unsigned* Vs  = fsm + 2 * 64 * QS_STRIDE;
    __shared__ int msk[64];

    int bh = blockIdx.x;
    int b  = bh >> 3;
    int h  = bh & 7;
    int q0 = blockIdx.y * 64;

    int tid  = threadIdx.x;
    int warp = tid >> 5;
    int lane = tid & 31;
    int wr   = warp * 16;
    int lg   = lane >> 2;
    int lq   = lane & 3;

    for (int i = tid; i < 64 * 16; i += 128) {
        int r  = i >> 4;
        int c4 = (i & 15) * 4;
        int qr = q0 + r; if (qr > LL - 1) qr = LL - 1;
        float4 v = *(const float4*)&qkv[((size_t)(b * LL + qr)) * H3 + h * DHH + c4];
        Qs[r * QS_STRIDE + c4 + 0] = __float_as_uint(v.x * 0.125f);
        Qs[r * QS_STRIDE + c4 + 1] = __float_as_uint(v.y * 0.125f);
        Qs[r * QS_STRIDE + c4 + 2] = __float_as_uint(v.z * 0.125f);
        Qs[r * QS_STRIDE + c4 + 3] = __float_as_uint(v.w * 0.125f);
    }

    float oacc[8][4];
    #pragma unroll
    for (int nt = 0; nt < 8; nt++)
        #pragma unroll
        for (int r = 0; r < 4; r++) oacc[nt][r] = 0.0f;
    float m0 = -1e30f, m1 = -1e30f, l0 = 0.0f, l1 = 0.0f;

    for (int kt = 0; kt < LL; kt += 64) {
        __syncthreads();

        for (int i = tid; i < 64 * 16; i += 128) {
            int r  = i >> 4;
            int c4 = (i & 15) * 4;
            int kr = kt + r; if (kr > LL - 1) kr = LL - 1;
            const float* base = &qkv[((size_t)(b * LL + kr)) * H3 + h * DHH + c4];
            float4 kv = *(const float4*)(base + HH);
            float4 vv = *(const float4*)(base + 2 * HH);
            KPs[r * QS_STRIDE + c4 + 0] = __float_as_uint(kv.x);
            KPs[r * QS_STRIDE + c4 + 1] = __float_as_uint(kv.y);
            KPs[r * QS_STRIDE + c4 + 2] = __float_as_uint(kv.z);
            KPs[r * QS_STRIDE + c4 + 3] = __float_as_uint(kv.w);
            Vs[r * VS_STRIDE + c4 + 0] = __float_as_uint(vv.x);
            Vs[r * VS_STRIDE + c4 + 1] = __float_as_uint(vv.y);
            Vs[r * VS_STRIDE + c4 + 2] = __float_as_uint(vv.z);
            Vs[r * VS_STRIDE + c4 + 3] = __float_as_uint(vv.w);
        }
        if (tid < 64) msk[tid] = (kt + tid < LL) ? mask[b * LL + kt + tid] : 0;
        __syncthreads();

        float sacc[8][4];
        #pragma unroll
        for (int nt = 0; nt < 8; nt++)
            #pragma unroll
            for (int r = 0; r < 4; r++) sacc[nt][r] = 0.0f;

        #pragma unroll
        for (int ks = 0; ks < 8; ks++) {
            int kb = ks * 8;
            unsigned af[4];
            af[0] = Qs[(wr + lg)     * QS_STRIDE + kb + lq];
            af[1] = Qs[(wr + lg + 8) * QS_STRIDE + kb + lq];
            af[2] = Qs[(wr + lg)     * QS_STRIDE + kb + lq + 4];
            af[3] = Qs[(wr + lg + 8) * QS_STRIDE + kb + lq + 4];
            #pragma unroll
            for (int nt = 0; nt < 8; nt++) {
                unsigned bf[2];
                bf[0] = KPs[(nt * 8 + lg) * QS_STRIDE + kb + lq];
                bf[1] = KPs[(nt * 8 + lg) * QS_STRIDE + kb + lq + 4];
                mma_tf32(sacc[nt], af, bf);
            }
        }

        float rmax0 = -1e30f, rmax1 = -1e30f;
        #pragma unroll
        for (int nt = 0; nt < 8; nt++) {
            #pragma unroll
            for (int j = 0; j < 2; j++) {
                int kl = nt * 8 + 2 * lq + j;
                bool ok = (kt + kl < LL) && (msk[kl] > 0);
                if (!ok) { sacc[nt][j] = -1e30f; sacc[nt][2 + j] = -1e30f; }
                rmax0 = fmaxf(rmax0, sacc[nt][j]);
                rmax1 = fmaxf(rmax1, sacc[nt][2 + j]);
            }
        }
        #pragma unroll
        for (int o = 1; o <= 2; o <<= 1) {
            rmax0 = fmaxf(rmax0, __shfl_xor_sync(0xffffffffu, rmax0, o));
            rmax1 = fmaxf(rmax1, __shfl_xor_sync(0xffffffffu, rmax1, o));
        }

        float m0n = fmaxf(m0, rmax0);
        float m1n = fmaxf(m1, rmax1);
        float alpha0 = __expf(m0 - m0n);
        float alpha1 = __expf(m1 - m1n);
        m0 = m0n; m1 = m1n;

        float rs0 = 0.0f, rs1 = 0.0f;
        #pragma unroll
        for (int nt = 0; nt < 8; nt++) {
            #pragma unroll
            for (int j = 0; j < 2; j++) {
                float p0 = __expf(sacc[nt][j] - m0);
                float p1 = __expf(sacc[nt][2 + j] - m1);
                sacc[nt][j] = p0;     rs0 += p0;
                sacc[nt][2 + j] = p1; rs1 += p1;
            }
        }
        #pragma unroll
        for (int o = 1; o <= 2; o <<= 1) {
            rs0 += __shfl_xor_sync(0xffffffffu, rs0, o);
            rs1 += __shfl_xor_sync(0xffffffffu, rs1, o);
        }
        l0 = l0 * alpha0 + rs0;
        l1 = l1 * alpha1 + rs1;

        #pragma unroll
        for (int nt = 0; nt < 8; nt++) {
            oacc[nt][0] *= alpha0; oacc[nt][1] *= alpha0;
            oacc[nt][2] *= alpha1; oacc[nt][3] *= alpha1;
        }

        __syncthreads();

        #pragma unroll
        for (int nt = 0; nt < 8; nt++) {
            int c = nt * 8 + 2 * lq;
            KPs[(wr + lg)     * QS_STRIDE + c]     = f2tf32(sacc[nt][0]);
            KPs[(wr + lg)     * QS_STRIDE + c + 1] = f2tf32(sacc[nt][1]);
            KPs[(wr + lg + 8) * QS_STRIDE + c]     = f2tf32(sacc[nt][2]);
            KPs[(wr + lg + 8) * QS_STRIDE + c + 1] = f2tf32(sacc[nt][3]);
        }
        __syncwarp();

        #pragma unroll
        for (int ks = 0; ks < 8; ks++) {
            int kb = ks * 8;
            unsigned af[4];
            af[0] = KPs[(wr + lg)     * QS_STRIDE + kb + lq];
            af[1] = KPs[(wr + lg + 8) * QS_STRIDE + kb + lq];
            af[2] = KPs[(wr + lg)     * QS_STRIDE + kb + lq + 4];
            af[3] = KPs[(wr + lg + 8) * QS_STRIDE + kb + lq + 4];
            #pragma unroll
            for (int nt = 0; nt < 8; nt++) {
                unsigned bf[2];
                bf[0] = Vs[(kb + lq)     * VS_STRIDE + nt * 8 + lg];
                bf[1] = Vs[(kb + lq + 4) * VS_STRIDE + nt * 8 + lg];
                mma_tf32(oacc[nt], af, bf);
            }
        }
    }

    float inv0 = 1.0f / fmaxf(l0, 1e-30f);
    float inv1 = 1.0f / fmaxf(l1, 1e-30f);
    int r0 = q0 + wr + lg;
    int r1 = r0 + 8;
    #pragma unroll
    for (int nt = 0; nt < 8; nt++) {
        int c = nt * 8 + 2 * lq;
        if (r0 < LL)
            *(float2*)&attout[((size_t)(b * LL + r0)) * HH + h * DHH + c] =
                make_float2(round_tf32(oacc[nt][0] * inv0), round_tf32(oacc[nt][1] * inv0));
        if (r1 < LL)
            *(float2*)&attout[((size_t)(b * LL + r1)) * HH + h * DHH + c] =
                make_float2(round_tf32(oacc[nt][2] * inv1), round_tf32(oacc[nt][3] * inv1));
    }
}

// ---------------------------------------------------------------------------
// Launch
// ---------------------------------------------------------------------------
extern "C" void kernel_launch(void* const* d_in, const int* in_sizes, int n_in,
                              void* d_out, int out_size) {
    const float* x         = (const float*)d_in[0];
    const int*   mask      = (const int*)  d_in[1];
    const float* conv_ln_g = (const float*)d_in[2];
    const float* conv_ln_b = (const float*)d_in[3];
    const float* dw_w      = (const float*)d_in[4];
    const float* dw_b      = (const float*)d_in[5];
    const float* pw_w      = (const float*)d_in[6];
    const float* pw_b      = (const float*)d_in[7];
    const float* att_ln_g  = (const float*)d_in[8];
    const float* att_ln_b  = (const float*)d_in[9];
    const float* qkv_w     = (const float*)d_in[10];
    const float* qkv_b     = (const float*)d_in[11];
    const float* out_w     = (const float*)d_in[12];
    const float* out_b     = (const float*)d_in[13];
    const float* ff_ln_g   = (const float*)d_in[14];
    const float* ff_ln_b   = (const float*)d_in[15];
    const float* ff_w      = (const float*)d_in[16];
    const float* ff_b      = (const float*)d_in[17];
    float* out = (float*)d_out;

    float *norm, *dwout, *qkv, *attout, *wt;
    cudaGetSymbolAddress((void**)&norm,   g_norm);
    cudaGetSymbolAddress((void**)&dwout,  g_dwout);
    cudaGetSymbolAddress((void**)&qkv,    g_qkv);
    cudaGetSymbolAddress((void**)&attout, g_attout);
    cudaGetSymbolAddress((void**)&wt,     g_wt);

    cudaFuncSetAttribute(flash_kernel,
                         cudaFuncAttributeMaxDynamicSharedMemorySize, FLASH_SMEM);
    cudaFuncSetAttribute(gemm_tf32_kernel<true, true, false>,
                         cudaFuncAttributeMaxDynamicSharedMemorySize, GEMM_SMEM);
    cudaFuncSetAttribute(gemm_tf32_kernel<false, false, true>,
                         cudaFuncAttributeMaxDynamicSharedMemorySize, GEMM_SMEM);
    cudaFuncSetAttribute(gemm_tf32_kernel<false, true, false>,
                         cudaFuncAttributeMaxDynamicSharedMemorySize, GEMM_SMEM);

    const int elems = MM * HH;

    // Pre-round all GEMM weights (single launch)
    round_all_w_kernel<<<(WT_TOT / 4 + 255) / 256, 256>>>(pw_w, qkv_w, out_w, ff_w, wt);

    add_pe_kernel<<<(elems + 255) / 256, 256>>>(x, out);

    for (int i = 0; i < NCC; i++) {
        ln_kernel<false><<<MM, 128>>>(out, norm, conv_ln_g + i * HH, conv_ln_b + i * HH);
        dwconv_kernel<<<(elems + 255) / 256, 256>>>(norm, dwout,
                                                    dw_w + i * HH * KW, dw_b + i * HH);
        gemm_tf32_kernel<true, true, false><<<dim3(HH / 128, MM / 128), 256, GEMM_SMEM>>>(
            dwout, wt + WT_PW + (size_t)i * HH * HH, pw_b + i * HH, out, out, MM, HH, HH);
    }

    ln_kernel<true><<<MM, 128>>>(out, norm, att_ln_g, att_ln_b);
    gemm_tf32_kernel<false, false, true><<<dim3(H3 / 128, MM / 128), 256, GEMM_SMEM>>>(
        norm, wt + WT_QKV, qkv_b, nullptr, qkv, MM, H3, HH);

    flash_kernel<<<dim3(BB * NHH, (LL + 63) / 64), 128, FLASH_SMEM>>>(qkv, mask, attout);

    gemm_tf32_kernel<false, true, false><<<dim3(HH / 128, MM / 128), 256, GEMM_SMEM>>>(
        attout, wt + WT_OUT, out_b, out, out, MM, HH, HH);

    ln_kernel<true><<<MM, 128>>>(out, norm, ff_ln_g, ff_ln_b);
    gemm_tf32_kernel<true, true, false><<<dim3(HH / 128, MM / 128), 256, GEMM_SMEM>>>(
        norm, wt + WT_FF, ff_b, out, out, MM, HH, HH);
}

// round 7
// speedup vs baseline: 1.1831x; 1.1274x over previous
#include <cuda_runtime.h>
#include <math.h>

// Problem constants
#define BB   32
#define LL   400
#define HH   512
#define NHH  8
#define DHH  64
#define KW   7
#define NCC  4
#define MM   (BB * LL)      // 12800 tokens
#define H3   (3 * HH)       // 1536

// ---------------------------------------------------------------------------
// Scratch
// ---------------------------------------------------------------------------
__device__ float g_norm  [MM * HH];
__device__ float g_dwout [MM * HH];
__device__ float g_qkv   [MM * H3];
__device__ float g_attout[MM * HH];
// pre-rounded (tf32) weights: pw | qkv | out | ff
#define WT_PW   0
#define WT_QKV  (NCC * HH * HH)
#define WT_OUT  (WT_QKV + H3 * HH)
#define WT_FF   (WT_OUT + HH * HH)
#define WT_TOT  (WT_FF + HH * HH)
__device__ float g_wt[WT_TOT];

// ---------------------------------------------------------------------------
// tf32 helpers
// ---------------------------------------------------------------------------
__device__ __forceinline__ unsigned f2tf32(float x) {
    unsigned r;
    asm("cvt.rna.tf32.f32 %0, %1;" : "=r"(r) : "f"(x));
    return r;
}
__device__ __forceinline__ float round_tf32(float x) {
    return __uint_as_float(f2tf32(x));
}

__device__ __forceinline__ void mma_tf32(float* d, const unsigned* a, const unsigned* b) {
    asm volatile(
        "mma.sync.aligned.m16n8k8.row.col.f32.tf32.tf32.f32 "
        "{%0,%1,%2,%3}, {%4,%5,%6,%7}, {%8,%9}, {%0,%1,%2,%3};\n"
        : "+f"(d[0]), "+f"(d[1]), "+f"(d[2]), "+f"(d[3])
        : "r"(a[0]), "r"(a[1]), "r"(a[2]), "r"(a[3]), "r"(b[0]), "r"(b[1]));
}

__device__ __forceinline__ void cp_async16(void* smem_dst, const void* gsrc) {
    unsigned sa = (unsigned)__cvta_generic_to_shared(smem_dst);
    asm volatile("cp.async.cg.shared.global [%0], [%1], 16;\n" :: "r"(sa), "l"(gsrc));
}

// ---------------------------------------------------------------------------
// Merged weight pre-round (one launch).
// ---------------------------------------------------------------------------
__global__ void round_all_w_kernel(const float* __restrict__ pw,
                                   const float* __restrict__ qkvw,
                                   const float* __restrict__ ow,
                                   const float* __restrict__ ffw,
                                   float* __restrict__ out) {
    int i = blockIdx.x * blockDim.x + threadIdx.x;
    const int n_pw  = WT_QKV / 4;
    const int n_qkv = (WT_OUT - WT_QKV) / 4;
    const int n_o   = (WT_FF - WT_OUT) / 4;
    const int n_tot = WT_TOT / 4;
    if (i >= n_tot) return;
    const float* src; int off;
    if (i < n_pw)                     { src = pw;   off = i; }
    else if (i < n_pw + n_qkv)        { src = qkvw; off = i - n_pw; }
    else if (i < n_pw + n_qkv + n_o)  { src = ow;   off = i - n_pw - n_qkv; }
    else                              { src = ffw;  off = i - n_pw - n_qkv - n_o; }
    float4 v = ((const float4*)src)[off];
    v.x = round_tf32(v.x); v.y = round_tf32(v.y);
    v.z = round_tf32(v.z); v.w = round_tf32(v.w);
    ((float4*)out)[i] = v;
}

// ---------------------------------------------------------------------------
// out = x + positional encoding
// ---------------------------------------------------------------------------
__global__ void add_pe_kernel(const float* __restrict__ x, float* __restrict__ out) {
    int idx = blockIdx.x * blockDim.x + threadIdx.x;
    if (idx >= MM * HH) return;
    int h = idx & (HH - 1);
    int l = (idx / HH) % LL;
    float freq = expf(-(float)(h & ~1) * (9.210340371976184f / (float)HH));
    float a = (float)l * freq;
    float pe = (h & 1) ? cosf(a) : sinf(a);
    out[idx] = x[idx] + pe;
}

// ---------------------------------------------------------------------------
// LayerNorm (standalone; attention/FF paths). TF32OUT rounds output.
// ---------------------------------------------------------------------------
template <bool TF32OUT>
__global__ void ln_kernel(const float* __restrict__ in, float* __restrict__ out,
                          const float* __restrict__ gw, const float* __restrict__ gb) {
    int row = blockIdx.x;
    int t   = threadIdx.x;  // 128
    const float4* p = (const float4*)(in + (size_t)row * HH);
    float4 v = p[t];

    __shared__ float sh[4];

    float s = v.x + v.y + v.z + v.w;
    #pragma unroll
    for (int o = 16; o > 0; o >>= 1) s += __shfl_down_sync(0xffffffffu, s, o);
    if ((t & 31) == 0) sh[t >> 5] = s;
    __syncthreads();
    float mean = (sh[0] + sh[1] + sh[2] + sh[3]) * (1.0f / HH);
    __syncthreads();

    float dx = v.x - mean, dy = v.y - mean, dz = v.z - mean, dw = v.w - mean;
    float q = dx * dx + dy * dy + dz * dz + dw * dw;
    #pragma unroll
    for (int o = 16; o > 0; o >>= 1) q += __shfl_down_sync(0xffffffffu, q, o);
    if ((t & 31) == 0) sh[t >> 5] = q;
    __syncthreads();
    float var  = (sh[0] + sh[1] + sh[2] + sh[3]) * (1.0f / HH);
    float rstd = rsqrtf(var + 1e-5f);

    float4 g4 = ((const float4*)gw)[t];
    float4 b4 = ((const float4*)gb)[t];
    float4 o4;
    o4.x = dx * rstd * g4.x + b4.x;
    o4.y = dy * rstd * g4.y + b4.y;
    o4.z = dz * rstd * g4.z + b4.z;
    o4.w = dw * rstd * g4.w + b4.w;
    if (TF32OUT) {
        o4.x = round_tf32(o4.x); o4.y = round_tf32(o4.y);
        o4.z = round_tf32(o4.z); o4.w = round_tf32(o4.w);
    }
    ((float4*)(out + (size_t)row * HH))[t] = o4;
}

// ---------------------------------------------------------------------------
// Fused LayerNorm + depthwise conv (K=7, pad 3).
// Block = (batch, 16-row L-tile), 256 threads. Smem holds LN output for the
// tile + 3-row halos (22 rows x 512). Out-of-range halo rows are zeroed
// (matches reference zero padding). Output tf32-rounded (feeds GEMM A).
// ---------------------------------------------------------------------------
#define CTILE 16
#define CHALO 3
#define CROWS (CTILE + 2 * CHALO)   // 22

__global__ void __launch_bounds__(256)
ln_dwconv_kernel(const float* __restrict__ in, float* __restrict__ dwout,
                 const float* __restrict__ gw, const float* __restrict__ gb,
                 const float* __restrict__ w, const float* __restrict__ bias) {
    __shared__ float sm[CROWS * HH];

    int b    = blockIdx.x;
    int t0   = blockIdx.y * CTILE;
    int tid  = threadIdx.x;
    int warp = tid >> 5;
    int lane = tid & 31;

    // Phase 1: LN for 22 rows, warp-per-row
    for (int rr = warp; rr < CROWS; rr += 8) {
        int l = t0 - CHALO + rr;
        if (l < 0 || l >= LL) {
            #pragma unroll
            for (int j = 0; j < 4; j++)
                *(float4*)&sm[rr * HH + lane * 4 + j * 128] = make_float4(0.f, 0.f, 0.f, 0.f);
            continue;
        }
        const float4* p = (const float4*)(in + ((size_t)(b * LL + l)) * HH);
        float4 v[4];
        float s = 0.0f;
        #pragma unroll
        for (int j = 0; j < 4; j++) {
            v[j] = p[lane + j * 32];
            s += v[j].x + v[j].y + v[j].z + v[j].w;
        }
        #pragma unroll
        for (int o = 16; o > 0; o >>= 1) s += __shfl_xor_sync(0xffffffffu, s, o);
        float mean = s * (1.0f / HH);

        float q = 0.0f;
        #pragma unroll
        for (int j = 0; j < 4; j++) {
            float dx = v[j].x - mean, dy = v[j].y - mean;
            float dz = v[j].z - mean, dw = v[j].w - mean;
            q += dx * dx + dy * dy + dz * dz + dw * dw;
        }
        #pragma unroll
        for (int o = 16; o > 0; o >>= 1) q += __shfl_xor_sync(0xffffffffu, q, o);
        float rstd = rsqrtf(q * (1.0f / HH) + 1e-5f);

        #pragma unroll
        for (int j = 0; j < 4; j++) {
            int c = lane * 4 + j * 128;
            float4 g4 = *(const float4*)&gw[c];
            float4 b4 = *(const float4*)&gb[c];
            float4 o4;
            o4.x = (v[j].x - mean) * rstd * g4.x + b4.x;
            o4.y = (v[j].y - mean) * rstd * g4.y + b4.y;
            o4.z = (v[j].z - mean) * rstd * g4.z + b4.z;
            o4.w = (v[j].w - mean) * rstd * g4.w + b4.w;
            *(float4*)&sm[rr * HH + c] = o4;
        }
    }
    __syncthreads();

    // Phase 2: depthwise conv, 2 channels x 16 rows per thread
    int c0 = tid * 2;   // 0..510
    float wr0[KW], wr1[KW];
    #pragma unroll
    for (int k = 0; k < KW; k++) {
        wr0[k] = w[c0 * KW + k];
        wr1[k] = w[(c0 + 1) * KW + k];
    }
    float bi0 = bias[c0], bi1 = bias[c0 + 1];

    #pragma unroll 4
    for (int r = 0; r < CTILE; r++) {
        float a0 = bi0, a1 = bi1;
        #pragma unroll
        for (int k = 0; k < KW; k++) {
            float2 x = *(const float2*)&sm[(r + k) * HH + c0];
            a0 += x.x * wr0[k];
            a1 += x.y * wr1[k];
        }
        *(float2*)&dwout[((size_t)(b * LL + t0 + r)) * HH + c0] =
            make_float2(round_tf32(a0), round_tf32(a1));
    }
}

// ---------------------------------------------------------------------------
// tf32 tensor-core GEMM: BM=128, BN=128, BK=32, double-buffered cp.async,
// one __syncthreads per k-iteration. A/W pre-rounded tf32.
// ---------------------------------------------------------------------------
#define GEMM_SS    (128 * 36)
#define GEMM_SMEM  (2 * GEMM_SS * 2 * 4)       // 73728 bytes

template <bool RELU, bool RES, bool TF32OUT>
__global__ void __launch_bounds__(256, 2)
gemm_tf32_kernel(const float* __restrict__ A, const float* __restrict__ W,
                 const float* __restrict__ bias, const float* __restrict__ R,
                 float* __restrict__ C, int Md, int Nd, int Kd) {
    extern __shared__ float gsm[];
    float* Asm = gsm;
    float* Bsm = gsm + 2 * GEMM_SS;

    int tid  = threadIdx.x;
    int m0   = blockIdx.y * 128;
    int n0   = blockIdx.x * 128;
    int warp = tid >> 5;
    int lane = tid & 31;
    int wm   = (warp >> 2) * 64;
    int wn   = (warp & 3) * 32;
    int lg   = lane >> 2;
    int lq   = lane & 3;

    int lrow = tid >> 2;
    int lc   = (tid & 3) * 8;

    const float* Ag0 = &A[(size_t)(m0 + lrow)      * Kd + lc];
    const float* Ag1 = &A[(size_t)(m0 + 64 + lrow) * Kd + lc];
    const float* Wg0 = &W[(size_t)(n0 + lrow)      * Kd + lc];
    const float* Wg1 = &W[(size_t)(n0 + 64 + lrow) * Kd + lc];

    float acc[4][4][4];
    #pragma unroll
    for (int i = 0; i < 4; i++)
        #pragma unroll
        for (int j = 0; j < 4; j++)
            #pragma unroll
            for (int r = 0; r < 4; r++) acc[i][j][r] = 0.0f;

    float* a_d0 = Asm + lrow * 36 + lc;
    float* a_d1 = Asm + (64 + lrow) * 36 + lc;
    float* b_d0 = Bsm + lrow * 36 + lc;
    float* b_d1 = Bsm + (64 + lrow) * 36 + lc;

    #define LOAD_STAGE(s, ko)                                                   \
    {                                                                           \
        int so = (s) * GEMM_SS;                                                 \
        cp_async16(a_d0 + so,     Ag0 + (ko));                                  \
        cp_async16(a_d0 + so + 4, Ag0 + (ko) + 4);                              \
        cp_async16(a_d1 + so,     Ag1 + (ko));                                  \
        cp_async16(a_d1 + so + 4, Ag1 + (ko) + 4);                              \
        cp_async16(b_d0 + so,     Wg0 + (ko));                                  \
        cp_async16(b_d0 + so + 4, Wg0 + (ko) + 4);                              \
        cp_async16(b_d1 + so,     Wg1 + (ko));                                  \
        cp_async16(b_d1 + so + 4, Wg1 + (ko) + 4);                              \
        asm volatile("cp.async.commit_group;\n");                               \
    }

    LOAD_STAGE(0, 0);

    int nit = Kd >> 5;
    for (int it = 0; it < nit; it++) {
        asm volatile("cp.async.wait_group 0;\n");
        __syncthreads();
        if (it + 1 < nit) LOAD_STAGE((it + 1) & 1, (it + 1) << 5);

        int cur = it & 1;
        const float* Asc = Asm + cur * GEMM_SS;
        const float* Bsc = Bsm + cur * GEMM_SS;

        #pragma unroll
        for (int ks = 0; ks < 4; ks++) {
            int kb = ks * 8;
            unsigned af[4][4], bf[4][2];
            #pragma unroll
            for (int mt = 0; mt < 4; mt++) {
                int mr = wm + mt * 16 + lg;
                af[mt][0] = __float_as_uint(Asc[mr * 36 + kb + lq]);
                af[mt][1] = __float_as_uint(Asc[(mr + 8) * 36 + kb + lq]);
                af[mt][2] = __float_as_uint(Asc[mr * 36 + kb + lq + 4]);
                af[mt][3] = __float_as_uint(Asc[(mr + 8) * 36 + kb + lq + 4]);
            }
            #pragma unroll
            for (int nt = 0; nt < 4; nt++) {
                int nr = wn + nt * 8 + lg;
                bf[nt][0] = __float_as_uint(Bsc[nr * 36 + kb + lq]);
                bf[nt][1] = __float_as_uint(Bsc[nr * 36 + kb + lq + 4]);
            }
            #pragma unroll
            for (int mt = 0; mt < 4; mt++)
                #pragma unroll
                for (int nt = 0; nt < 4; nt++)
                    mma_tf32(acc[mt][nt], af[mt], bf[nt]);
        }
    }
    #undef LOAD_STAGE

    #pragma unroll
    for (int mt = 0; mt < 4; mt++) {
        #pragma unroll
        for (int half = 0; half < 2; half++) {
            int m = m0 + wm + mt * 16 + lg + half * 8;
            #pragma unroll
            for (int nt = 0; nt < 4; nt++) {
                int n = n0 + wn + nt * 8 + 2 * lq;
                float v0 = acc[mt][nt][half * 2 + 0] + bias[n];
                float v1 = acc[mt][nt][half * 2 + 1] + bias[n + 1];
                if (RELU) { v0 = fmaxf(v0, 0.0f); v1 = fmaxf(v1, 0.0f); }
                if (RES)  { v0 += R[(size_t)m * Nd + n]; v1 += R[(size_t)m * Nd + n + 1]; }
                if (TF32OUT) { v0 = round_tf32(v0); v1 = round_tf32(v1); }
                *(float2*)&C[(size_t)m * Nd + n] = make_float2(v0, v1);
            }
        }
    }
}

// ---------------------------------------------------------------------------
// Fused flash attention (tf32 MMA, online softmax). qkv pre-rounded tf32.
// ---------------------------------------------------------------------------
#define QS_STRIDE 68
#define VS_STRIDE 72
#define FLASH_SMEM ((64 * QS_STRIDE * 2 + 64 * VS_STRIDE) * 4)

__global__ void __launch_bounds__(128)
flash_kernel(const float* __restrict__ qkv, const int* __restrict__ mask,
             float* __restrict__ attout) {
    extern __shared__ unsigned fsm[];
    unsigned* Qs  = fsm;
    unsigned* KPs = fsm + 64 * QS_STRIDE;
    unsigned* Vs  = fsm + 2 * 64 * QS_STRIDE;
    __shared__ int msk[64];

    int bh = blockIdx.x;
    int b  = bh >> 3;
    int h  = bh & 7;
    int q0 = blockIdx.y * 64;

    int tid  = threadIdx.x;
    int warp = tid >> 5;
    int lane = tid & 31;
    int wr   = warp * 16;
    int lg   = lane >> 2;
    int lq   = lane & 3;

    for (int i = tid; i < 64 * 16; i += 128) {
        int r  = i >> 4;
        int c4 = (i & 15) * 4;
        int qr = q0 + r; if (qr > LL - 1) qr = LL - 1;
        float4 v = *(const float4*)&qkv[((size_t)(b * LL + qr)) * H3 + h * DHH + c4];
        Qs[r * QS_STRIDE + c4 + 0] = __float_as_uint(v.x * 0.125f);
        Qs[r * QS_STRIDE + c4 + 1] = __float_as_uint(v.y * 0.125f);
        Qs[r * QS_STRIDE + c4 + 2] = __float_as_uint(v.z * 0.125f);
        Qs[r * QS_STRIDE + c4 + 3] = __float_as_uint(v.w * 0.125f);
    }

    float oacc[8][4];
    #pragma unroll
    for (int nt = 0; nt < 8; nt++)
        #pragma unroll
        for (int r = 0; r < 4; r++) oacc[nt][r] = 0.0f;
    float m0 = -1e30f, m1 = -1e30f, l0 = 0.0f, l1 = 0.0f;

    for (int kt = 0; kt < LL; kt += 64) {
        __syncthreads();

        for (int i = tid; i < 64 * 16; i += 128) {
            int r  = i >> 4;
            int c4 = (i & 15) * 4;
            int kr = kt + r; if (kr > LL - 1) kr = LL - 1;
            const float* base = &qkv[((size_t)(b * LL + kr)) * H3 + h * DHH + c4];
            float4 kv = *(const float4*)(base + HH);
            float4 vv = *(const float4*)(base + 2 * HH);
            KPs[r * QS_STRIDE + c4 + 0] = __float_as_uint(kv.x);
            KPs[r * QS_STRIDE + c4 + 1] = __float_as_uint(kv.y);
            KPs[r * QS_STRIDE + c4 + 2] = __float_as_uint(kv.z);
            KPs[r * QS_STRIDE + c4 + 3] = __float_as_uint(kv.w);
            Vs[r * VS_STRIDE + c4 + 0] = __float_as_uint(vv.x);
            Vs[r * VS_STRIDE + c4 + 1] = __float_as_uint(vv.y);
            Vs[r * VS_STRIDE + c4 + 2] = __float_as_uint(vv.z);
            Vs[r * VS_STRIDE + c4 + 3] = __float_as_uint(vv.w);
        }
        if (tid < 64) msk[tid] = (kt + tid < LL) ? mask[b * LL + kt + tid] : 0;
        __syncthreads();

        float sacc[8][4];
        #pragma unroll
        for (int nt = 0; nt < 8; nt++)
            #pragma unroll
            for (int r = 0; r < 4; r++) sacc[nt][r] = 0.0f;

        #pragma unroll
        for (int ks = 0; ks < 8; ks++) {
            int kb = ks * 8;
            unsigned af[4];
            af[0] = Qs[(wr + lg)     * QS_STRIDE + kb + lq];
            af[1] = Qs[(wr + lg + 8) * QS_STRIDE + kb + lq];
            af[2] = Qs[(wr + lg)     * QS_STRIDE + kb + lq + 4];
            af[3] = Qs[(wr + lg + 8) * QS_STRIDE + kb + lq + 4];
            #pragma unroll
            for (int nt = 0; nt < 8; nt++) {
                unsigned bf[2];
                bf[0] = KPs[(nt * 8 + lg) * QS_STRIDE + kb + lq];
                bf[1] = KPs[(nt * 8 + lg) * QS_STRIDE + kb + lq + 4];
                mma_tf32(sacc[nt], af, bf);
            }
        }

        float rmax0 = -1e30f, rmax1 = -1e30f;
        #pragma unroll
        for (int nt = 0; nt < 8; nt++) {
            #pragma unroll
            for (int j = 0; j < 2; j++) {
                int kl = nt * 8 + 2 * lq + j;
                bool ok = (kt + kl < LL) && (msk[kl] > 0);
                if (!ok) { sacc[nt][j] = -1e30f; sacc[nt][2 + j] = -1e30f; }
                rmax0 = fmaxf(rmax0, sacc[nt][j]);
                rmax1 = fmaxf(rmax1, sacc[nt][2 + j]);
            }
        }
        #pragma unroll
        for (int o = 1; o <= 2; o <<= 1) {
            rmax0 = fmaxf(rmax0, __shfl_xor_sync(0xffffffffu, rmax0, o));
            rmax1 = fmaxf(rmax1, __shfl_xor_sync(0xffffffffu, rmax1, o));
        }

        float m0n = fmaxf(m0, rmax0);
        float m1n = fmaxf(m1, rmax1);
        float alpha0 = __expf(m0 - m0n);
        float alpha1 = __expf(m1 - m1n);
        m0 = m0n; m1 = m1n;

        float rs0 = 0.0f, rs1 = 0.0f;
        #pragma unroll
        for (int nt = 0; nt < 8; nt++) {
            #pragma unroll
            for (int j = 0; j < 2; j++) {
                float p0 = __expf(sacc[nt][j] - m0);
                float p1 = __expf(sacc[nt][2 + j] - m1);
                sacc[nt][j] = p0;     rs0 += p0;
                sacc[nt][2 + j] = p1; rs1 += p1;
            }
        }
        #pragma unroll
        for (int o = 1; o <= 2; o <<= 1) {
            rs0 += __shfl_xor_sync(0xffffffffu, rs0, o);
            rs1 += __shfl_xor_sync(0xffffffffu, rs1, o);
        }
        l0 = l0 * alpha0 + rs0;
        l1 = l1 * alpha1 + rs1;

        #pragma unroll
        for (int nt = 0; nt < 8; nt++) {
            oacc[nt][0] *= alpha0; oacc[nt][1] *= alpha0;
            oacc[nt][2] *= alpha1; oacc[nt][3] *= alpha1;
        }

        __syncthreads();

        #pragma unroll
        for (int nt = 0; nt < 8; nt++) {
            int c = nt * 8 + 2 * lq;
            KPs[(wr + lg)     * QS_STRIDE + c]     = f2tf32(sacc[nt][0]);
            KPs[(wr + lg)     * QS_STRIDE + c + 1] = f2tf32(sacc[nt][1]);
            KPs[(wr + lg + 8) * QS_STRIDE + c]     = f2tf32(sacc[nt][2]);
            KPs[(wr + lg + 8) * QS_STRIDE + c + 1] = f2tf32(sacc[nt][3]);
        }
        __syncwarp();

        #pragma unroll
        for (int ks = 0; ks < 8; ks++) {
            int kb = ks * 8;
            unsigned af[4];
            af[0] = KPs[(wr + lg)     * QS_STRIDE + kb + lq];
            af[1] = KPs[(wr + lg + 8) * QS_STRIDE + kb + lq];
            af[2] = KPs[(wr + lg)     * QS_STRIDE + kb + lq + 4];
            af[3] = KPs[(wr + lg + 8) * QS_STRIDE + kb + lq + 4];
            #pragma unroll
            for (int nt = 0; nt < 8; nt++) {
                unsigned bf[2];
                bf[0] = Vs[(kb + lq)     * VS_STRIDE + nt * 8 + lg];
                bf[1] = Vs[(kb + lq + 4) * VS_STRIDE + nt * 8 + lg];
                mma_tf32(oacc[nt], af, bf);
            }
        }
    }

    float inv0 = 1.0f / fmaxf(l0, 1e-30f);
    float inv1 = 1.0f / fmaxf(l1, 1e-30f);
    int r0 = q0 + wr + lg;
    int r1 = r0 + 8;
    #pragma unroll
    for (int nt = 0; nt < 8; nt++) {
        int c = nt * 8 + 2 * lq;
        if (r0 < LL)
            *(float2*)&attout[((size_t)(b * LL + r0)) * HH + h * DHH + c] =
                make_float2(round_tf32(oacc[nt][0] * inv0), round_tf32(oacc[nt][1] * inv0));
        if (r1 < LL)
            *(float2*)&attout[((size_t)(b * LL + r1)) * HH + h * DHH + c] =
                make_float2(round_tf32(oacc[nt][2] * inv1), round_tf32(oacc[nt][3] * inv1));
    }
}

// ---------------------------------------------------------------------------
// Launch
// ---------------------------------------------------------------------------
extern "C" void kernel_launch(void* const* d_in, const int* in_sizes, int n_in,
                              void* d_out, int out_size) {
    const float* x         = (const float*)d_in[0];
    const int*   mask      = (const int*)  d_in[1];
    const float* conv_ln_g = (const float*)d_in[2];
    const float* conv_ln_b = (const float*)d_in[3];
    const float* dw_w      = (const float*)d_in[4];
    const float* dw_b      = (const float*)d_in[5];
    const float* pw_w      = (const float*)d_in[6];
    const float* pw_b      = (const float*)d_in[7];
    const float* att_ln_g  = (const float*)d_in[8];
    const float* att_ln_b  = (const float*)d_in[9];
    const float* qkv_w     = (const float*)d_in[10];
    const float* qkv_b     = (const float*)d_in[11];
    const float* out_w     = (const float*)d_in[12];
    const float* out_b     = (const float*)d_in[13];
    const float* ff_ln_g   = (const float*)d_in[14];
    const float* ff_ln_b   = (const float*)d_in[15];
    const float* ff_w      = (const float*)d_in[16];
    const float* ff_b      = (const float*)d_in[17];
    float* out = (float*)d_out;

    float *norm, *dwout, *qkv, *attout, *wt;
    cudaGetSymbolAddress((void**)&norm,   g_norm);
    cudaGetSymbolAddress((void**)&dwout,  g_dwout);
    cudaGetSymbolAddress((void**)&qkv,    g_qkv);
    cudaGetSymbolAddress((void**)&attout, g_attout);
    cudaGetSymbolAddress((void**)&wt,     g_wt);

    cudaFuncSetAttribute(flash_kernel,
                         cudaFuncAttributeMaxDynamicSharedMemorySize, FLASH_SMEM);
    cudaFuncSetAttribute(gemm_tf32_kernel<true, true, false>,
                         cudaFuncAttributeMaxDynamicSharedMemorySize, GEMM_SMEM);
    cudaFuncSetAttribute(gemm_tf32_kernel<false, false, true>,
                         cudaFuncAttributeMaxDynamicSharedMemorySize, GEMM_SMEM);
    cudaFuncSetAttribute(gemm_tf32_kernel<false, true, false>,
                         cudaFuncAttributeMaxDynamicSharedMemorySize, GEMM_SMEM);

    const int elems = MM * HH;

    round_all_w_kernel<<<(WT_TOT / 4 + 255) / 256, 256>>>(pw_w, qkv_w, out_w, ff_w, wt);

    add_pe_kernel<<<(elems + 255) / 256, 256>>>(x, out);

    for (int i = 0; i < NCC; i++) {
        ln_dwconv_kernel<<<dim3(BB, LL / CTILE), 256>>>(
            out, dwout, conv_ln_g + i * HH, conv_ln_b + i * HH,
            dw_w + i * HH * KW, dw_b + i * HH);
        gemm_tf32_kernel<true, true, false><<<dim3(HH / 128, MM / 128), 256, GEMM_SMEM>>>(
            dwout, wt + WT_PW + (size_t)i * HH * HH, pw_b + i * HH, out, out, MM, HH, HH);
    }

    ln_kernel<true><<<MM, 128>>>(out, norm, att_ln_g, att_ln_b);
    gemm_tf32_kernel<false, false, true><<<dim3(H3 / 128, MM / 128), 256, GEMM_SMEM>>>(
        norm, wt + WT_QKV, qkv_b, nullptr, qkv, MM, H3, HH);

    flash_kernel<<<dim3(BB * NHH, (LL + 63) / 64), 128, FLASH_SMEM>>>(qkv, mask, attout);

    gemm_tf32_kernel<false, true, false><<<dim3(HH / 128, MM / 128), 256, GEMM_SMEM>>>(
        attout, wt + WT_OUT, out_b, out, out, MM, HH, HH);

    ln_kernel<true><<<MM, 128>>>(out, norm, ff_ln_g, ff_ln_b);
    gemm_tf32_kernel<true, true, false><<<dim3(HH / 128, MM / 128), 256, GEMM_SMEM>>>(
        norm, wt + WT_FF, ff_b, out, out, MM, HH, HH);
}

// round 8
// speedup vs baseline: 1.1841x; 1.0008x over previous
#include <cuda_runtime.h>
#include <math.h>

// Problem constants
#define BB   32
#define LL   400
#define HH   512
#define NHH  8
#define DHH  64
#define KW   7
#define NCC  4
#define MM   (BB * LL)      // 12800 tokens
#define H3   (3 * HH)       // 1536

// ---------------------------------------------------------------------------
// Scratch
// ---------------------------------------------------------------------------
__device__ float g_norm  [MM * HH];
__device__ float g_dwout [MM * HH];
__device__ float g_qkv   [MM * H3];
__device__ float g_attout[MM * HH];
// pre-rounded (tf32) weights: pw | qkv | out | ff
#define WT_PW   0
#define WT_QKV  (NCC * HH * HH)
#define WT_OUT  (WT_QKV + H3 * HH)
#define WT_FF   (WT_OUT + HH * HH)
#define WT_TOT  (WT_FF + HH * HH)
__device__ float g_wt[WT_TOT];

// ---------------------------------------------------------------------------
// tf32 helpers
// ---------------------------------------------------------------------------
__device__ __forceinline__ unsigned f2tf32(float x) {
    unsigned r;
    asm("cvt.rna.tf32.f32 %0, %1;" : "=r"(r) : "f"(x));
    return r;
}
__device__ __forceinline__ float round_tf32(float x) {
    return __uint_as_float(f2tf32(x));
}

__device__ __forceinline__ void mma_tf32(float* d, const unsigned* a, const unsigned* b) {
    asm volatile(
        "mma.sync.aligned.m16n8k8.row.col.f32.tf32.tf32.f32 "
        "{%0,%1,%2,%3}, {%4,%5,%6,%7}, {%8,%9}, {%0,%1,%2,%3};\n"
        : "+f"(d[0]), "+f"(d[1]), "+f"(d[2]), "+f"(d[3])
        : "r"(a[0]), "r"(a[1]), "r"(a[2]), "r"(a[3]), "r"(b[0]), "r"(b[1]));
}

__device__ __forceinline__ void cp_async16(void* smem_dst, const void* gsrc) {
    unsigned sa = (unsigned)__cvta_generic_to_shared(smem_dst);
    asm volatile("cp.async.cg.shared.global [%0], [%1], 16;\n" :: "r"(sa), "l"(gsrc));
}

// ---------------------------------------------------------------------------
// Merged weight pre-round (one launch).
// ---------------------------------------------------------------------------
__global__ void round_all_w_kernel(const float* __restrict__ pw,
                                   const float* __restrict__ qkvw,
                                   const float* __restrict__ ow,
                                   const float* __restrict__ ffw,
                                   float* __restrict__ out) {
    int i = blockIdx.x * blockDim.x + threadIdx.x;
    const int n_pw  = WT_QKV / 4;
    const int n_qkv = (WT_OUT - WT_QKV) / 4;
    const int n_o   = (WT_FF - WT_OUT) / 4;
    const int n_tot = WT_TOT / 4;
    if (i >= n_tot) return;
    const float* src; int off;
    if (i < n_pw)                     { src = pw;   off = i; }
    else if (i < n_pw + n_qkv)        { src = qkvw; off = i - n_pw; }
    else if (i < n_pw + n_qkv + n_o)  { src = ow;   off = i - n_pw - n_qkv; }
    else                              { src = ffw;  off = i - n_pw - n_qkv - n_o; }
    float4 v = ((const float4*)src)[off];
    v.x = round_tf32(v.x); v.y = round_tf32(v.y);
    v.z = round_tf32(v.z); v.w = round_tf32(v.w);
    ((float4*)out)[i] = v;
}

// ---------------------------------------------------------------------------
// out = x + positional encoding
// ---------------------------------------------------------------------------
__global__ void add_pe_kernel(const float* __restrict__ x, float* __restrict__ out) {
    int idx = blockIdx.x * blockDim.x + threadIdx.x;
    if (idx >= MM * HH) return;
    int h = idx & (HH - 1);
    int l = (idx / HH) % LL;
    float freq = expf(-(float)(h & ~1) * (9.210340371976184f / (float)HH));
    float a = (float)l * freq;
    float pe = (h & 1) ? cosf(a) : sinf(a);
    out[idx] = x[idx] + pe;
}

// ---------------------------------------------------------------------------
// LayerNorm (standalone; attention/FF paths). TF32OUT rounds output.
// ---------------------------------------------------------------------------
template <bool TF32OUT>
__global__ void ln_kernel(const float* __restrict__ in, float* __restrict__ out,
                          const float* __restrict__ gw, const float* __restrict__ gb) {
    int row = blockIdx.x;
    int t   = threadIdx.x;  // 128
    const float4* p = (const float4*)(in + (size_t)row * HH);
    float4 v = p[t];

    __shared__ float sh[4];

    float s = v.x + v.y + v.z + v.w;
    #pragma unroll
    for (int o = 16; o > 0; o >>= 1) s += __shfl_down_sync(0xffffffffu, s, o);
    if ((t & 31) == 0) sh[t >> 5] = s;
    __syncthreads();
    float mean = (sh[0] + sh[1] + sh[2] + sh[3]) * (1.0f / HH);
    __syncthreads();

    float dx = v.x - mean, dy = v.y - mean, dz = v.z - mean, dw = v.w - mean;
    float q = dx * dx + dy * dy + dz * dz + dw * dw;
    #pragma unroll
    for (int o = 16; o > 0; o >>= 1) q += __shfl_down_sync(0xffffffffu, q, o);
    if ((t & 31) == 0) sh[t >> 5] = q;
    __syncthreads();
    float var  = (sh[0] + sh[1] + sh[2] + sh[3]) * (1.0f / HH);
    float rstd = rsqrtf(var + 1e-5f);

    float4 g4 = ((const float4*)gw)[t];
    float4 b4 = ((const float4*)gb)[t];
    float4 o4;
    o4.x = dx * rstd * g4.x + b4.x;
    o4.y = dy * rstd * g4.y + b4.y;
    o4.z = dz * rstd * g4.z + b4.z;
    o4.w = dw * rstd * g4.w + b4.w;
    if (TF32OUT) {
        o4.x = round_tf32(o4.x); o4.y = round_tf32(o4.y);
        o4.z = round_tf32(o4.z); o4.w = round_tf32(o4.w);
    }
    ((float4*)(out + (size_t)row * HH))[t] = o4;
}

// ---------------------------------------------------------------------------
// Fused LayerNorm + depthwise conv (K=7, pad 3).
// ---------------------------------------------------------------------------
#define CTILE 16
#define CHALO 3
#define CROWS (CTILE + 2 * CHALO)   // 22

__global__ void __launch_bounds__(256)
ln_dwconv_kernel(const float* __restrict__ in, float* __restrict__ dwout,
                 const float* __restrict__ gw, const float* __restrict__ gb,
                 const float* __restrict__ w, const float* __restrict__ bias) {
    __shared__ float sm[CROWS * HH];

    int b    = blockIdx.x;
    int t0   = blockIdx.y * CTILE;
    int tid  = threadIdx.x;
    int warp = tid >> 5;
    int lane = tid & 31;

    for (int rr = warp; rr < CROWS; rr += 8) {
        int l = t0 - CHALO + rr;
        if (l < 0 || l >= LL) {
            #pragma unroll
            for (int j = 0; j < 4; j++)
                *(float4*)&sm[rr * HH + lane * 4 + j * 128] = make_float4(0.f, 0.f, 0.f, 0.f);
            continue;
        }
        const float4* p = (const float4*)(in + ((size_t)(b * LL + l)) * HH);
        float4 v[4];
        float s = 0.0f;
        #pragma unroll
        for (int j = 0; j < 4; j++) {
            v[j] = p[lane + j * 32];
            s += v[j].x + v[j].y + v[j].z + v[j].w;
        }
        #pragma unroll
        for (int o = 16; o > 0; o >>= 1) s += __shfl_xor_sync(0xffffffffu, s, o);
        float mean = s * (1.0f / HH);

        float q = 0.0f;
        #pragma unroll
        for (int j = 0; j < 4; j++) {
            float dx = v[j].x - mean, dy = v[j].y - mean;
            float dz = v[j].z - mean, dw = v[j].w - mean;
            q += dx * dx + dy * dy + dz * dz + dw * dw;
        }
        #pragma unroll
        for (int o = 16; o > 0; o >>= 1) q += __shfl_xor_sync(0xffffffffu, q, o);
        float rstd = rsqrtf(q * (1.0f / HH) + 1e-5f);

        #pragma unroll
        for (int j = 0; j < 4; j++) {
            int c = lane * 4 + j * 128;
            float4 g4 = *(const float4*)&gw[c];
            float4 b4 = *(const float4*)&gb[c];
            float4 o4;
            o4.x = (v[j].x - mean) * rstd * g4.x + b4.x;
            o4.y = (v[j].y - mean) * rstd * g4.y + b4.y;
            o4.z = (v[j].z - mean) * rstd * g4.z + b4.z;
            o4.w = (v[j].w - mean) * rstd * g4.w + b4.w;
            *(float4*)&sm[rr * HH + c] = o4;
        }
    }
    __syncthreads();

    int c0 = tid * 2;
    float wr0[KW], wr1[KW];
    #pragma unroll
    for (int k = 0; k < KW; k++) {
        wr0[k] = w[c0 * KW + k];
        wr1[k] = w[(c0 + 1) * KW + k];
    }
    float bi0 = bias[c0], bi1 = bias[c0 + 1];

    #pragma unroll 4
    for (int r = 0; r < CTILE; r++) {
        float a0 = bi0, a1 = bi1;
        #pragma unroll
        for (int k = 0; k < KW; k++) {
            float2 x = *(const float2*)&sm[(r + k) * HH + c0];
            a0 += x.x * wr0[k];
            a1 += x.y * wr1[k];
        }
        *(float2*)&dwout[((size_t)(b * LL + t0 + r)) * HH + c0] =
            make_float2(round_tf32(a0), round_tf32(a1));
    }
}

// ---------------------------------------------------------------------------
// tf32 tensor-core GEMM: BM=128, BN=128, BK=32, 3-stage cp.async pipeline,
// XOR-swizzled smem (stride 32, no padding), one barrier per k-iteration.
// A/W pre-rounded tf32. 256 threads (8 warps, 2x4), warp tile 64x32.
// Swizzle: col' = col ^ ((row&7)<<2). Fragment rows satisfy row&7 == lg, so
// reads use xor = lg<<2; banks lq | ((lg<<2)^kb) cover all 32 — conflict-free.
// ---------------------------------------------------------------------------
#define GEMM_NSTG  3
#define GEMM_SS    (128 * 32)                    // floats per stage per array
#define GEMM_SMEM  (GEMM_NSTG * GEMM_SS * 2 * 4) // 98304 bytes

template <bool RELU, bool RES, bool TF32OUT>
__global__ void __launch_bounds__(256, 2)
gemm_tf32_kernel(const float* __restrict__ A, const float* __restrict__ W,
                 const float* __restrict__ bias, const float* __restrict__ R,
                 float* __restrict__ C, int Md, int Nd, int Kd) {
    extern __shared__ float gsm[];
    float* Asm = gsm;                          // [3][128][32] swizzled
    float* Bsm = gsm + GEMM_NSTG * GEMM_SS;    // [3][128][32] swizzled

    int tid  = threadIdx.x;
    int m0   = blockIdx.y * 128;
    int n0   = blockIdx.x * 128;
    int warp = tid >> 5;
    int lane = tid & 31;
    int wm   = (warp >> 2) * 64;
    int wn   = (warp & 3) * 32;
    int lg   = lane >> 2;
    int lq   = lane & 3;
    int xv   = lg << 2;           // fragment-read swizzle

    int lrow = tid >> 2;          // 0..63
    int lc   = (tid & 3) * 8;     // 0,8,16,24
    int swz  = (lrow & 7) << 2;   // store-side swizzle (same for lrow and 64+lrow)
    int sc0  = lc ^ swz;
    int sc1  = (lc + 4) ^ swz;

    const float* Ag0 = &A[(size_t)(m0 + lrow)      * Kd + lc];
    const float* Ag1 = &A[(size_t)(m0 + 64 + lrow) * Kd + lc];
    const float* Wg0 = &W[(size_t)(n0 + lrow)      * Kd + lc];
    const float* Wg1 = &W[(size_t)(n0 + 64 + lrow) * Kd + lc];

    float acc[4][4][4];
    #pragma unroll
    for (int i = 0; i < 4; i++)
        #pragma unroll
        for (int j = 0; j < 4; j++)
            #pragma unroll
            for (int r = 0; r < 4; r++) acc[i][j][r] = 0.0f;

    #define LOAD_STAGE(s, ko)                                                   \
    {                                                                           \
        float* As_ = Asm + (s) * GEMM_SS;                                       \
        float* Bs_ = Bsm + (s) * GEMM_SS;                                       \
        cp_async16(As_ + lrow * 32 + sc0,        Ag0 + (ko));                   \
        cp_async16(As_ + lrow * 32 + sc1,        Ag0 + (ko) + 4);               \
        cp_async16(As_ + (64 + lrow) * 32 + sc0, Ag1 + (ko));                   \
        cp_async16(As_ + (64 + lrow) * 32 + sc1, Ag1 + (ko) + 4);               \
        cp_async16(Bs_ + lrow * 32 + sc0,        Wg0 + (ko));                   \
        cp_async16(Bs_ + lrow * 32 + sc1,        Wg0 + (ko) + 4);               \
        cp_async16(Bs_ + (64 + lrow) * 32 + sc0, Wg1 + (ko));                   \
        cp_async16(Bs_ + (64 + lrow) * 32 + sc1, Wg1 + (ko) + 4);               \
        asm volatile("cp.async.commit_group;\n");                               \
    }

    int nit = Kd >> 5;   // BK=32
    LOAD_STAGE(0, 0);
    if (nit > 1) LOAD_STAGE(1, 32);

    for (int it = 0; it < nit; it++) {
        if (it + 1 < nit)
            asm volatile("cp.async.wait_group 1;\n");
        else
            asm volatile("cp.async.wait_group 0;\n");
        __syncthreads();
        if (it + 2 < nit) LOAD_STAGE((it + 2) % GEMM_NSTG, (it + 2) << 5);

        int cur = it % GEMM_NSTG;
        const float* Asc = Asm + cur * GEMM_SS;
        const float* Bsc = Bsm + cur * GEMM_SS;

        #pragma unroll
        for (int ks = 0; ks < 4; ks++) {
            int kb = ks * 8;
            int cA = (kb + lq) ^ xv;
            int cB = (kb + lq + 4) ^ xv;
            unsigned af[4][4], bf[4][2];
            #pragma unroll
            for (int mt = 0; mt < 4; mt++) {
                int mr = wm + mt * 16 + lg;
                af[mt][0] = __float_as_uint(Asc[mr * 32 + cA]);
                af[mt][1] = __float_as_uint(Asc[(mr + 8) * 32 + cA]);
                af[mt][2] = __float_as_uint(Asc[mr * 32 + cB]);
                af[mt][3] = __float_as_uint(Asc[(mr + 8) * 32 + cB]);
            }
            #pragma unroll
            for (int nt = 0; nt < 4; nt++) {
                int nr = wn + nt * 8 + lg;
                bf[nt][0] = __float_as_uint(Bsc[nr * 32 + cA]);
                bf[nt][1] = __float_as_uint(Bsc[nr * 32 + cB]);
            }
            #pragma unroll
            for (int mt = 0; mt < 4; mt++)
                #pragma unroll
                for (int nt = 0; nt < 4; nt++)
                    mma_tf32(acc[mt][nt], af[mt], bf[nt]);
        }
    }
    #undef LOAD_STAGE

    #pragma unroll
    for (int mt = 0; mt < 4; mt++) {
        #pragma unroll
        for (int half = 0; half < 2; half++) {
            int m = m0 + wm + mt * 16 + lg + half * 8;
            #pragma unroll
            for (int nt = 0; nt < 4; nt++) {
                int n = n0 + wn + nt * 8 + 2 * lq;
                float v0 = acc[mt][nt][half * 2 + 0] + bias[n];
                float v1 = acc[mt][nt][half * 2 + 1] + bias[n + 1];
                if (RELU) { v0 = fmaxf(v0, 0.0f); v1 = fmaxf(v1, 0.0f); }
                if (RES)  { v0 += R[(size_t)m * Nd + n]; v1 += R[(size_t)m * Nd + n + 1]; }
                if (TF32OUT) { v0 = round_tf32(v0); v1 = round_tf32(v1); }
                *(float2*)&C[(size_t)m * Nd + n] = make_float2(v0, v1);
            }
        }
    }
}

// ---------------------------------------------------------------------------
// Fused flash attention (tf32 MMA, online softmax). qkv pre-rounded tf32.
// ---------------------------------------------------------------------------
#define QS_STRIDE 68
#define VS_STRIDE 72
#define FLASH_SMEM ((64 * QS_STRIDE * 2 + 64 * VS_STRIDE) * 4)

__global__ void __launch_bounds__(128)
flash_kernel(const float* __restrict__ qkv, const int* __restrict__ mask,
             float* __restrict__ attout) {
    extern __shared__ unsigned fsm[];
    unsigned* Qs  = fsm;
    unsigned* KPs = fsm + 64 * QS_STRIDE;
    unsigned* Vs  = fsm + 2 * 64 * QS_STRIDE;
    __shared__ int msk[64];

    int bh = blockIdx.x;
    int b  = bh >> 3;
    int h  = bh & 7;
    int q0 = blockIdx.y * 64;

    int tid  = threadIdx.x;
    int warp = tid >> 5;
    int lane = tid & 31;
    int wr   = warp * 16;
    int lg   = lane >> 2;
    int lq   = lane & 3;

    for (int i = tid; i < 64 * 16; i += 128) {
        int r  = i >> 4;
        int c4 = (i & 15) * 4;
        int qr = q0 + r; if (qr > LL - 1) qr = LL - 1;
        float4 v = *(const float4*)&qkv[((size_t)(b * LL + qr)) * H3 + h * DHH + c4];
        Qs[r * QS_STRIDE + c4 + 0] = __float_as_uint(v.x * 0.125f);
        Qs[r * QS_STRIDE + c4 + 1] = __float_as_uint(v.y * 0.125f);
        Qs[r * QS_STRIDE + c4 + 2] = __float_as_uint(v.z * 0.125f);
        Qs[r * QS_STRIDE + c4 + 3] = __float_as_uint(v.w * 0.125f);
    }

    float oacc[8][4];
    #pragma unroll
    for (int nt = 0; nt < 8; nt++)
        #pragma unroll
        for (int r = 0; r < 4; r++) oacc[nt][r] = 0.0f;
    float m0 = -1e30f, m1 = -1e30f, l0 = 0.0f, l1 = 0.0f;

    for (int kt = 0; kt < LL; kt += 64) {
        __syncthreads();

        for (int i = tid; i < 64 * 16; i += 128) {
            int r  = i >> 4;
            int c4 = (i & 15) * 4;
            int kr = kt + r; if (kr > LL - 1) kr = LL - 1;
            const float* base = &qkv[((size_t)(b * LL + kr)) * H3 + h * DHH + c4];
            float4 kv = *(const float4*)(base + HH);
            float4 vv = *(const float4*)(base + 2 * HH);
            KPs[r * QS_STRIDE + c4 + 0] = __float_as_uint(kv.x);
            KPs[r * QS_STRIDE + c4 + 1] = __float_as_uint(kv.y);
            KPs[r * QS_STRIDE + c4 + 2] = __float_as_uint(kv.z);
            KPs[r * QS_STRIDE + c4 + 3] = __float_as_uint(kv.w);
            Vs[r * VS_STRIDE + c4 + 0] = __float_as_uint(vv.x);
            Vs[r * VS_STRIDE + c4 + 1] = __float_as_uint(vv.y);
            Vs[r * VS_STRIDE + c4 + 2] = __float_as_uint(vv.z);
            Vs[r * VS_STRIDE + c4 + 3] = __float_as_uint(vv.w);
        }
        if (tid < 64) msk[tid] = (kt + tid < LL) ? mask[b * LL + kt + tid] : 0;
        __syncthreads();

        float sacc[8][4];
        #pragma unroll
        for (int nt = 0; nt < 8; nt++)
            #pragma unroll
            for (int r = 0; r < 4; r++) sacc[nt][r] = 0.0f;

        #pragma unroll
        for (int ks = 0; ks < 8; ks++) {
            int kb = ks * 8;
            unsigned af[4];
            af[0] = Qs[(wr + lg)     * QS_STRIDE + kb + lq];
            af[1] = Qs[(wr + lg + 8) * QS_STRIDE + kb + lq];
            af[2] = Qs[(wr + lg)     * QS_STRIDE + kb + lq + 4];
            af[3] = Qs[(wr + lg + 8) * QS_STRIDE + kb + lq + 4];
            #pragma unroll
            for (int nt = 0; nt < 8; nt++) {
                unsigned bf[2];
                bf[0] = KPs[(nt * 8 + lg) * QS_STRIDE + kb + lq];
                bf[1] = KPs[(nt * 8 + lg) * QS_STRIDE + kb + lq + 4];
                mma_tf32(sacc[nt], af, bf);
            }
        }

        float rmax0 = -1e30f, rmax1 = -1e30f;
        #pragma unroll
        for (int nt = 0; nt < 8; nt++) {
            #pragma unroll
            for (int j = 0; j < 2; j++) {
                int kl = nt * 8 + 2 * lq + j;
                bool ok = (kt + kl < LL) && (msk[kl] > 0);
                if (!ok) { sacc[nt][j] = -1e30f; sacc[nt][2 + j] = -1e30f; }
                rmax0 = fmaxf(rmax0, sacc[nt][j]);
                rmax1 = fmaxf(rmax1, sacc[nt][2 + j]);
            }
        }
        #pragma unroll
        for (int o = 1; o <= 2; o <<= 1) {
            rmax0 = fmaxf(rmax0, __shfl_xor_sync(0xffffffffu, rmax0, o));
            rmax1 = fmaxf(rmax1, __shfl_xor_sync(0xffffffffu, rmax1, o));
        }

        float m0n = fmaxf(m0, rmax0);
        float m1n = fmaxf(m1, rmax1);
        float alpha0 = __expf(m0 - m0n);
        float alpha1 = __expf(m1 - m1n);
        m0 = m0n; m1 = m1n;

        float rs0 = 0.0f, rs1 = 0.0f;
        #pragma unroll
        for (int nt = 0; nt < 8; nt++) {
            #pragma unroll
            for (int j = 0; j < 2; j++) {
                float p0 = __expf(sacc[nt][j] - m0);
                float p1 = __expf(sacc[nt][2 + j] - m1);
                sacc[nt][j] = p0;     rs0 += p0;
                sacc[nt][2 + j] = p1; rs1 += p1;
            }
        }
        #pragma unroll
        for (int o = 1; o <= 2; o <<= 1) {
            rs0 += __shfl_xor_sync(0xffffffffu, rs0, o);
            rs1 += __shfl_xor_sync(0xffffffffu, rs1, o);
        }
        l0 = l0 * alpha0 + rs0;
        l1 = l1 * alpha1 + rs1;

        #pragma unroll
        for (int nt = 0; nt < 8; nt++) {
            oacc[nt][0] *= alpha0; oacc[nt][1] *= alpha0;
            oacc[nt][2] *= alpha1; oacc[nt][3] *= alpha1;
        }

        __syncthreads();

        #pragma unroll
        for (int nt = 0; nt < 8; nt++) {
            int c = nt * 8 + 2 * lq;
            KPs[(wr + lg)     * QS_STRIDE + c]     = f2tf32(sacc[nt][0]);
            KPs[(wr + lg)     * QS_STRIDE + c + 1] = f2tf32(sacc[nt][1]);
            KPs[(wr + lg + 8) * QS_STRIDE + c]     = f2tf32(sacc[nt][2]);
            KPs[(wr + lg + 8) * QS_STRIDE + c + 1] = f2tf32(sacc[nt][3]);
        }
        __syncwarp();

        #pragma unroll
        for (int ks = 0; ks < 8; ks++) {
            int kb = ks * 8;
            unsigned af[4];
            af[0] = KPs[(wr + lg)     * QS_STRIDE + kb + lq];
            af[1] = KPs[(wr + lg + 8) * QS_STRIDE + kb + lq];
            af[2] = KPs[(wr + lg)     * QS_STRIDE + kb + lq + 4];
            af[3] = KPs[(wr + lg + 8) * QS_STRIDE + kb + lq + 4];
            #pragma unroll
            for (int nt = 0; nt < 8; nt++) {
                unsigned bf[2];
                bf[0] = Vs[(kb + lq)     * VS_STRIDE + nt * 8 + lg];
                bf[1] = Vs[(kb + lq + 4) * VS_STRIDE + nt * 8 + lg];
                mma_tf32(oacc[nt], af, bf);
            }
        }
    }

    float inv0 = 1.0f / fmaxf(l0, 1e-30f);
    float inv1 = 1.0f / fmaxf(l1, 1e-30f);
    int r0 = q0 + wr + lg;
    int r1 = r0 + 8;
    #pragma unroll
    for (int nt = 0; nt < 8; nt++) {
        int c = nt * 8 + 2 * lq;
        if (r0 < LL)
            *(float2*)&attout[((size_t)(b * LL + r0)) * HH + h * DHH + c] =
                make_float2(round_tf32(oacc[nt][0] * inv0), round_tf32(oacc[nt][1] * inv0));
        if (r1 < LL)
            *(float2*)&attout[((size_t)(b * LL + r1)) * HH + h * DHH + c] =
                make_float2(round_tf32(oacc[nt][2] * inv1), round_tf32(oacc[nt][3] * inv1));
    }
}

// ---------------------------------------------------------------------------
// Launch
// ---------------------------------------------------------------------------
extern "C" void kernel_launch(void* const* d_in, const int* in_sizes, int n_in,
                              void* d_out, int out_size) {
    const float* x         = (const float*)d_in[0];
    const int*   mask      = (const int*)  d_in[1];
    const float* conv_ln_g = (const float*)d_in[2];
    const float* conv_ln_b = (const float*)d_in[3];
    const float* dw_w      = (const float*)d_in[4];
    const float* dw_b      = (const float*)d_in[5];
    const float* pw_w      = (const float*)d_in[6];
    const float* pw_b      = (const float*)d_in[7];
    const float* att_ln_g  = (const float*)d_in[8];
    const float* att_ln_b  = (const float*)d_in[9];
    const float* qkv_w     = (const float*)d_in[10];
    const float* qkv_b     = (const float*)d_in[11];
    const float* out_w     = (const float*)d_in[12];
    const float* out_b     = (const float*)d_in[13];
    const float* ff_ln_g   = (const float*)d_in[14];
    const float* ff_ln_b   = (const float*)d_in[15];
    const float* ff_w      = (const float*)d_in[16];
    const float* ff_b      = (const float*)d_in[17];
    float* out = (float*)d_out;

    float *norm, *dwout, *qkv, *attout, *wt;
    cudaGetSymbolAddress((void**)&norm,   g_norm);
    cudaGetSymbolAddress((void**)&dwout,  g_dwout);
    cudaGetSymbolAddress((void**)&qkv,    g_qkv);
    cudaGetSymbolAddress((void**)&attout, g_attout);
    cudaGetSymbolAddress((void**)&wt,     g_wt);

    cudaFuncSetAttribute(flash_kernel,
                         cudaFuncAttributeMaxDynamicSharedMemorySize, FLASH_SMEM);
    cudaFuncSetAttribute(gemm_tf32_kernel<true, true, false>,
                         cudaFuncAttributeMaxDynamicSharedMemorySize, GEMM_SMEM);
    cudaFuncSetAttribute(gemm_tf32_kernel<false, false, true>,
                         cudaFuncAttributeMaxDynamicSharedMemorySize, GEMM_SMEM);
    cudaFuncSetAttribute(gemm_tf32_kernel<false, true, false>,
                         cudaFuncAttributeMaxDynamicSharedMemorySize, GEMM_SMEM);

    const int elems = MM * HH;

    round_all_w_kernel<<<(WT_TOT / 4 + 255) / 256, 256>>>(pw_w, qkv_w, out_w, ff_w, wt);

    add_pe_kernel<<<(elems + 255) / 256, 256>>>(x, out);

    for (int i = 0; i < NCC; i++) {
        ln_dwconv_kernel<<<dim3(BB, LL / CTILE), 256>>>(
            out, dwout, conv_ln_g + i * HH, conv_ln_b + i * HH,
            dw_w + i * HH * KW, dw_b + i * HH);
        gemm_tf32_kernel<true, true, false><<<dim3(HH / 128, MM / 128), 256, GEMM_SMEM>>>(
            dwout, wt + WT_PW + (size_t)i * HH * HH, pw_b + i * HH, out, out, MM, HH, HH);
    }

    ln_kernel<true><<<MM, 128>>>(out, norm, att_ln_g, att_ln_b);
    gemm_tf32_kernel<false, false, true><<<dim3(H3 / 128, MM / 128), 256, GEMM_SMEM>>>(
        norm, wt + WT_QKV, qkv_b, nullptr, qkv, MM, H3, HH);

    flash_kernel<<<dim3(BB * NHH, (LL + 63) / 64), 128, FLASH_SMEM>>>(qkv, mask, attout);

    gemm_tf32_kernel<false, true, false><<<dim3(HH / 128, MM / 128), 256, GEMM_SMEM>>>(
        attout, wt + WT_OUT, out_b, out, out, MM, HH, HH);

    ln_kernel<true><<<MM, 128>>>(out, norm, ff_ln_g, ff_ln_b);
    gemm_tf32_kernel<true, true, false><<<dim3(HH / 128, MM / 128), 256, GEMM_SMEM>>>(
        norm, wt + WT_FF, ff_b, out, out, MM, HH, HH);
}

// round 10
// speedup vs baseline: 1.5920x; 1.3445x over previous
#include <cuda_runtime.h>
#include <cuda_fp16.h>
#include <math.h>
#include <stdint.h>

// Problem constants
#define BB   32
#define LL   400
#define HH   512
#define NHH  8
#define DHH  64
#define KW   7
#define NCC  4
#define MM   (BB * LL)      // 12800 tokens
#define H3   (3 * HH)       // 1536

// ---------------------------------------------------------------------------
// Scratch
// ---------------------------------------------------------------------------
__device__ __half g_norm_h [MM * HH];
__device__ __half g_dwout_h[MM * HH];
__device__ float  g_qkv    [MM * H3];
__device__ __half g_attout_h[MM * HH];
// fp16 weights: pw | qkv | out | ff
#define WT_PW   0
#define WT_QKV  (NCC * HH * HH)
#define WT_OUT  (WT_QKV + H3 * HH)
#define WT_FF   (WT_OUT + HH * HH)
#define WT_TOT  (WT_FF + HH * HH)
__device__ __half g_wth[WT_TOT];

// ---------------------------------------------------------------------------
// helpers
// ---------------------------------------------------------------------------
__device__ __forceinline__ unsigned f2tf32(float x) {
    unsigned r;
    asm("cvt.rna.tf32.f32 %0, %1;" : "=r"(r) : "f"(x));
    return r;
}
__device__ __forceinline__ float round_tf32(float x) {
    return __uint_as_float(f2tf32(x));
}

// legacy tf32 mma (still used in flash)
__device__ __forceinline__ void mma_tf32(float* d, const unsigned* a, const unsigned* b) {
    asm volatile(
        "mma.sync.aligned.m16n8k8.row.col.f32.tf32.tf32.f32 "
        "{%0,%1,%2,%3}, {%4,%5,%6,%7}, {%8,%9}, {%0,%1,%2,%3};\n"
        : "+f"(d[0]), "+f"(d[1]), "+f"(d[2]), "+f"(d[3])
        : "r"(a[0]), "r"(a[1]), "r"(a[2]), "r"(a[3]), "r"(b[0]), "r"(b[1]));
}

// fp16 mma, fp32 accumulate, m16n8k16
__device__ __forceinline__ void mma_f16(float* d, const unsigned* a, const unsigned* b) {
    asm volatile(
        "mma.sync.aligned.m16n8k16.row.col.f32.f16.f16.f32 "
        "{%0,%1,%2,%3}, {%4,%5,%6,%7}, {%8,%9}, {%0,%1,%2,%3};\n"
        : "+f"(d[0]), "+f"(d[1]), "+f"(d[2]), "+f"(d[3])
        : "r"(a[0]), "r"(a[1]), "r"(a[2]), "r"(a[3]), "r"(b[0]), "r"(b[1]));
}

__device__ __forceinline__ void cp_async16(void* smem_dst, const void* gsrc) {
    unsigned sa = (unsigned)__cvta_generic_to_shared(smem_dst);
    asm volatile("cp.async.cg.shared.global [%0], [%1], 16;\n" :: "r"(sa), "l"(gsrc));
}

// ---------------------------------------------------------------------------
// Weight pre-convert to fp16 (one launch).
// ---------------------------------------------------------------------------
__global__ void conv_all_w_kernel(const float* __restrict__ pw,
                                  const float* __restrict__ qkvw,
                                  const float* __restrict__ ow,
                                  const float* __restrict__ ffw,
                                  __half* __restrict__ out) {
    int i = blockIdx.x * blockDim.x + threadIdx.x;       // float4 index
    const int n_pw  = WT_QKV / 4;
    const int n_qkv = (WT_OUT - WT_QKV) / 4;
    const int n_o   = (WT_FF - WT_OUT) / 4;
    const int n_tot = WT_TOT / 4;
    if (i >= n_tot) return;
    const float* src; int off;
    if (i < n_pw)                     { src = pw;   off = i; }
    else if (i < n_pw + n_qkv)        { src = qkvw; off = i - n_pw; }
    else if (i < n_pw + n_qkv + n_o)  { src = ow;   off = i - n_pw - n_qkv; }
    else                              { src = ffw;  off = i - n_pw - n_qkv - n_o; }
    float4 v = ((const float4*)src)[off];
    __half2 h0 = __floats2half2_rn(v.x, v.y);
    __half2 h1 = __floats2half2_rn(v.z, v.w);
    ((__half2*)out)[i * 2]     = h0;
    ((__half2*)out)[i * 2 + 1] = h1;
}

// ---------------------------------------------------------------------------
// out = x + positional encoding
// ---------------------------------------------------------------------------
__global__ void add_pe_kernel(const float* __restrict__ x, float* __restrict__ out) {
    int idx = blockIdx.x * blockDim.x + threadIdx.x;
    if (idx >= MM * HH) return;
    int h = idx & (HH - 1);
    int l = (idx / HH) % LL;
    float freq = expf(-(float)(h & ~1) * (9.210340371976184f / (float)HH));
    float a = (float)l * freq;
    float pe = (h & 1) ? cosf(a) : sinf(a);
    out[idx] = x[idx] + pe;
}

// ---------------------------------------------------------------------------
// LayerNorm -> fp16 output (feeds GEMM A). One block/row, 128 thr.
// ---------------------------------------------------------------------------
__global__ void ln_h_kernel(const float* __restrict__ in, __half* __restrict__ out,
                            const float* __restrict__ gw, const float* __restrict__ gb) {
    int row = blockIdx.x;
    int t   = threadIdx.x;  // 128
    const float4* p = (const float4*)(in + (size_t)row * HH);
    float4 v = p[t];

    __shared__ float sh[4];

    float s = v.x + v.y + v.z + v.w;
    #pragma unroll
    for (int o = 16; o > 0; o >>= 1) s += __shfl_down_sync(0xffffffffu, s, o);
    if ((t & 31) == 0) sh[t >> 5] = s;
    __syncthreads();
    float mean = (sh[0] + sh[1] + sh[2] + sh[3]) * (1.0f / HH);
    __syncthreads();

    float dx = v.x - mean, dy = v.y - mean, dz = v.z - mean, dw = v.w - mean;
    float q = dx * dx + dy * dy + dz * dz + dw * dw;
    #pragma unroll
    for (int o = 16; o > 0; o >>= 1) q += __shfl_down_sync(0xffffffffu, q, o);
    if ((t & 31) == 0) sh[t >> 5] = q;
    __syncthreads();
    float var  = (sh[0] + sh[1] + sh[2] + sh[3]) * (1.0f / HH);
    float rstd = rsqrtf(var + 1e-5f);

    float4 g4 = ((const float4*)gw)[t];
    float4 b4 = ((const float4*)gb)[t];
    float ox = dx * rstd * g4.x + b4.x;
    float oy = dy * rstd * g4.y + b4.y;
    float oz = dz * rstd * g4.z + b4.z;
    float ow = dw * rstd * g4.w + b4.w;
    __half2* o2 = (__half2*)(out + (size_t)row * HH);
    o2[t * 2]     = __floats2half2_rn(ox, oy);
    o2[t * 2 + 1] = __floats2half2_rn(oz, ow);
}

// ---------------------------------------------------------------------------
// Fused LayerNorm + depthwise conv (K=7, pad 3) -> fp16 output.
// ---------------------------------------------------------------------------
#define CTILE 16
#define CHALO 3
#define CROWS (CTILE + 2 * CHALO)   // 22

__global__ void __launch_bounds__(256)
ln_dwconv_kernel(const float* __restrict__ in, __half* __restrict__ dwout,
                 const float* __restrict__ gw, const float* __restrict__ gb,
                 const float* __restrict__ w, const float* __restrict__ bias) {
    __shared__ float sm[CROWS * HH];

    int b    = blockIdx.x;
    int t0   = blockIdx.y * CTILE;
    int tid  = threadIdx.x;
    int warp = tid >> 5;
    int lane = tid & 31;

    for (int rr = warp; rr < CROWS; rr += 8) {
        int l = t0 - CHALO + rr;
        if (l < 0 || l >= LL) {
            #pragma unroll
            for (int j = 0; j < 4; j++)
                *(float4*)&sm[rr * HH + lane * 4 + j * 128] = make_float4(0.f, 0.f, 0.f, 0.f);
            continue;
        }
        const float4* p = (const float4*)(in + ((size_t)(b * LL + l)) * HH);
        float4 v[4];
        float s = 0.0f;
        #pragma unroll
        for (int j = 0; j < 4; j++) {
            v[j] = p[lane + j * 32];
            s += v[j].x + v[j].y + v[j].z + v[j].w;
        }
        #pragma unroll
        for (int o = 16; o > 0; o >>= 1) s += __shfl_xor_sync(0xffffffffu, s, o);
        float mean = s * (1.0f / HH);

        float q = 0.0f;
        #pragma unroll
        for (int j = 0; j < 4; j++) {
            float dx = v[j].x - mean, dy = v[j].y - mean;
            float dz = v[j].z - mean, dw = v[j].w - mean;
            q += dx * dx + dy * dy + dz * dz + dw * dw;
        }
        #pragma unroll
        for (int o = 16; o > 0; o >>= 1) q += __shfl_xor_sync(0xffffffffu, q, o);
        float rstd = rsqrtf(q * (1.0f / HH) + 1e-5f);

        #pragma unroll
        for (int j = 0; j < 4; j++) {
            int c = lane * 4 + j * 128;
            float4 g4 = *(const float4*)&gw[c];
            float4 b4 = *(const float4*)&gb[c];
            float4 o4;
            o4.x = (v[j].x - mean) * rstd * g4.x + b4.x;
            o4.y = (v[j].y - mean) * rstd * g4.y + b4.y;
            o4.z = (v[j].z - mean) * rstd * g4.z + b4.z;
            o4.w = (v[j].w - mean) * rstd * g4.w + b4.w;
            *(float4*)&sm[rr * HH + c] = o4;
        }
    }
    __syncthreads();

    int c0 = tid * 2;
    float wr0[KW], wr1[KW];
    #pragma unroll
    for (int k = 0; k < KW; k++) {
        wr0[k] = w[c0 * KW + k];
        wr1[k] = w[(c0 + 1) * KW + k];
    }
    float bi0 = bias[c0], bi1 = bias[c0 + 1];

    #pragma unroll 4
    for (int r = 0; r < CTILE; r++) {
        float a0 = bi0, a1 = bi1;
        #pragma unroll
        for (int k = 0; k < KW; k++) {
            float2 x = *(const float2*)&sm[(r + k) * HH + c0];
            a0 += x.x * wr0[k];
            a1 += x.y * wr1[k];
        }
        *(__half2*)&dwout[((size_t)(b * LL + t0 + r)) * HH + c0] =
            __floats2half2_rn(a0, a1);
    }
}

// ---------------------------------------------------------------------------
// fp16 tensor-core GEMM: C[m,n] = act( A[m,:].W[n,:] + bias[n] ) (+ R)
// BM=128, BN=128, BK=32 (halves), 3-stage cp.async, pad stride 20 words.
// 256 threads (8 warps 2x4), warp tile 64x32, m16n8k16, fp32 accumulate.
// ---------------------------------------------------------------------------
#define GH_ROWW  20                                 // b32 words per row (16 data + 4 pad)
#define GH_SS    (128 * GH_ROWW)                    // words per stage per array
#define GH_NSTG  3
#define GEMM_SMEM (GH_NSTG * GH_SS * 2 * 4)         // 61440 bytes

template <bool RELU, bool RES, bool TF32OUT>
__global__ void __launch_bounds__(256, 2)
gemm_f16_kernel(const __half* __restrict__ A, const __half* __restrict__ W,
                const float* __restrict__ bias, const float* __restrict__ R,
                float* __restrict__ C, int Md, int Nd, int Kd) {
    extern __shared__ unsigned gsm[];
    unsigned* Asm = gsm;                        // [3][128][20]
    unsigned* Bsm = gsm + GH_NSTG * GH_SS;      // [3][128][20]

    int tid  = threadIdx.x;
    int m0   = blockIdx.y * 128;
    int n0   = blockIdx.x * 128;
    int warp = tid >> 5;
    int lane = tid & 31;
    int wm   = (warp >> 2) * 64;
    int wn   = (warp & 3) * 32;
    int lg   = lane >> 2;
    int lq   = lane & 3;

    int lrow = tid >> 2;            // 0..63
    int lchunk = (tid & 3);         // 16B chunk (8 halves) within 64B row
    int sw = lrow * GH_ROWW + lchunk * 4;          // word offset row lrow
    int sw2 = (64 + lrow) * GH_ROWW + lchunk * 4;  // row lrow+64

    const __half* Ag0 = &A[(size_t)(m0 + lrow)      * Kd + lchunk * 8];
    const __half* Ag1 = &A[(size_t)(m0 + 64 + lrow) * Kd + lchunk * 8];
    const __half* Wg0 = &W[(size_t)(n0 + lrow)      * Kd + lchunk * 8];
    const __half* Wg1 = &W[(size_t)(n0 + 64 + lrow) * Kd + lchunk * 8];

    float acc[4][4][4];
    #pragma unroll
    for (int i = 0; i < 4; i++)
        #pragma unroll
        for (int j = 0; j < 4; j++)
            #pragma unroll
            for (int r = 0; r < 4; r++) acc[i][j][r] = 0.0f;

    #define LOAD_STAGE(s, ko)                                                   \
    {                                                                           \
        unsigned* As_ = Asm + (s) * GH_SS;                                      \
        unsigned* Bs_ = Bsm + (s) * GH_SS;                                      \
        cp_async16(As_ + sw,  Ag0 + (ko));                                      \
        cp_async16(As_ + sw2, Ag1 + (ko));                                      \
        cp_async16(Bs_ + sw,  Wg0 + (ko));                                      \
        cp_async16(Bs_ + sw2, Wg1 + (ko));                                      \
        asm volatile("cp.async.commit_group;\n");                               \
    }

    int nit = Kd >> 5;   // BK=32 halves
    LOAD_STAGE(0, 0);
    if (nit > 1) LOAD_STAGE(1, 32);

    for (int it = 0; it < nit; it++) {
        if (it + 1 < nit)
            asm volatile("cp.async.wait_group 1;\n");
        else
            asm volatile("cp.async.wait_group 0;\n");
        __syncthreads();
        if (it + 2 < nit) LOAD_STAGE((it + 2) % GH_NSTG, (it + 2) << 5);

        int cur = it % GH_NSTG;
        const unsigned* Asc = Asm + cur * GH_SS;
        const unsigned* Bsc = Bsm + cur * GH_SS;

        #pragma unroll
        for (int ks = 0; ks < 2; ks++) {
            int kb = ks * 8;   // half2-word base within 16-word row
            unsigned af[4][4], bf[4][2];
            #pragma unroll
            for (int mt = 0; mt < 4; mt++) {
                int mr = wm + mt * 16 + lg;
                af[mt][0] = Asc[mr * GH_ROWW + kb + lq];
                af[mt][1] = Asc[(mr + 8) * GH_ROWW + kb + lq];
                af[mt][2] = Asc[mr * GH_ROWW + kb + lq + 4];
                af[mt][3] = Asc[(mr + 8) * GH_ROWW + kb + lq + 4];
            }
            #pragma unroll
            for (int nt = 0; nt < 4; nt++) {
                int nr = wn + nt * 8 + lg;
                bf[nt][0] = Bsc[nr * GH_ROWW + kb + lq];
                bf[nt][1] = Bsc[nr * GH_ROWW + kb + lq + 4];
            }
            #pragma unroll
            for (int mt = 0; mt < 4; mt++)
                #pragma unroll
                for (int nt = 0; nt < 4; nt++)
                    mma_f16(acc[mt][nt], af[mt], bf[nt]);
        }
    }
    #undef LOAD_STAGE

    #pragma unroll
    for (int mt = 0; mt < 4; mt++) {
        #pragma unroll
        for (int half = 0; half < 2; half++) {
            int m = m0 + wm + mt * 16 + lg + half * 8;
            #pragma unroll
            for (int nt = 0; nt < 4; nt++) {
                int n = n0 + wn + nt * 8 + 2 * lq;
                float v0 = acc[mt][nt][half * 2 + 0] + bias[n];
                float v1 = acc[mt][nt][half * 2 + 1] + bias[n + 1];
                if (RELU) { v0 = fmaxf(v0, 0.0f); v1 = fmaxf(v1, 0.0f); }
                if (RES)  { v0 += R[(size_t)m * Nd + n]; v1 += R[(size_t)m * Nd + n + 1]; }
                if (TF32OUT) { v0 = round_tf32(v0); v1 = round_tf32(v1); }
                *(float2*)&C[(size_t)m * Nd + n] = make_float2(v0, v1);
            }
        }
    }
}

// ---------------------------------------------------------------------------
// fp16 GEMM variant writing fp16 C (for attout path producers) — not needed;
// attout comes from flash. (kept out intentionally)
// ---------------------------------------------------------------------------

// ---------------------------------------------------------------------------
// Fused flash attention (tf32 MMA, online softmax). qkv tf32-rounded fp32.
// Output: fp16 attout (feeds out-proj GEMM A).
// ---------------------------------------------------------------------------
#define QS_STRIDE 68
#define VS_STRIDE 72
#define FLASH_SMEM ((64 * QS_STRIDE * 2 + 64 * VS_STRIDE) * 4)

__global__ void __launch_bounds__(128)
flash_kernel(const float* __restrict__ qkv, const int* __restrict__ mask,
             __half* __restrict__ attout) {
    extern __shared__ unsigned fsm[];
    unsigned* Qs  = fsm;
    unsigned* KPs = fsm + 64 * QS_STRIDE;
    unsigned* Vs  = fsm + 2 * 64 * QS_STRIDE;
    __shared__ int msk[64];

    int bh = blockIdx.x;
    int b  = bh >> 3;
    int h  = bh & 7;
    int q0 = blockIdx.y * 64;

    int tid  = threadIdx.x;
    int warp = tid >> 5;
    int lane = tid & 31;
    int wr   = warp * 16;
    int lg   = lane >> 2;
    int lq   = lane & 3;

    for (int i = tid; i < 64 * 16; i += 128) {
        int r  = i >> 4;
        int c4 = (i & 15) * 4;
        int qr = q0 + r; if (qr > LL - 1) qr = LL - 1;
        float4 v = *(const float4*)&qkv[((size_t)(b * LL + qr)) * H3 + h * DHH + c4];
        Qs[r * QS_STRIDE + c4 + 0] = __float_as_uint(v.x * 0.125f);
        Qs[r * QS_STRIDE + c4 + 1] = __float_as_uint(v.y * 0.125f);
        Qs[r * QS_STRIDE + c4 + 2] = __float_as_uint(v.z * 0.125f);
        Qs[r * QS_STRIDE + c4 + 3] = __float_as_uint(v.w * 0.125f);
    }

    float oacc[8][4];
    #pragma unroll
    for (int nt = 0; nt < 8; nt++)
        #pragma unroll
        for (int r2 = 0; r2 < 4; r2++) oacc[nt][r2] = 0.0f;
    float m0 = -1e30f, m1 = -1e30f, l0 = 0.0f, l1 = 0.0f;

    for (int kt = 0; kt < LL; kt += 64) {
        __syncthreads();

        for (int i = tid; i < 64 * 16; i += 128) {
            int r  = i >> 4;
            int c4 = (i & 15) * 4;
            int kr = kt + r; if (kr > LL - 1) kr = LL - 1;
            const float* base = &qkv[((size_t)(b * LL + kr)) * H3 + h * DHH + c4];
            float4 kv = *(const float4*)(base + HH);
            float4 vv = *(const float4*)(base + 2 * HH);
            KPs[r * QS_STRIDE + c4 + 0] = __float_as_uint(kv.x);
            KPs[r * QS_STRIDE + c4 + 1] = __float_as_uint(kv.y);
            KPs[r * QS_STRIDE + c4 + 2] = __float_as_uint(kv.z);
            KPs[r * QS_STRIDE + c4 + 3] = __float_as_uint(kv.w);
            Vs[r * VS_STRIDE + c4 + 0] = __float_as_uint(vv.x);
            Vs[r * VS_STRIDE + c4 + 1] = __float_as_uint(vv.y);
            Vs[r * VS_STRIDE + c4 + 2] = __float_as_uint(vv.z);
            Vs[r * VS_STRIDE + c4 + 3] = __float_as_uint(vv.w);
        }
        if (tid < 64) msk[tid] = (kt + tid < LL) ? mask[b * LL + kt + tid] : 0;
        __syncthreads();

        float sacc[8][4];
        #pragma unroll
        for (int nt = 0; nt < 8; nt++)
            #pragma unroll
            for (int r2 = 0; r2 < 4; r2++) sacc[nt][r2] = 0.0f;

        #pragma unroll
        for (int ks = 0; ks < 8; ks++) {
            int kb = ks * 8;
            unsigned af[4];
            af[0] = Qs[(wr + lg)     * QS_STRIDE + kb + lq];
            af[1] = Qs[(wr + lg + 8) * QS_STRIDE + kb + lq];
            af[2] = Qs[(wr + lg)     * QS_STRIDE + kb + lq + 4];
            af[3] = Qs[(wr + lg + 8) * QS_STRIDE + kb + lq + 4];
            #pragma unroll
            for (int nt = 0; nt < 8; nt++) {
                unsigned bf[2];
                bf[0] = KPs[(nt * 8 + lg) * QS_STRIDE + kb + lq];
                bf[1] = KPs[(nt * 8 + lg) * QS_STRIDE + kb + lq + 4];
                mma_tf32(sacc[nt], af, bf);
            }
        }

        float rmax0 = -1e30f, rmax1 = -1e30f;
        #pragma unroll
        for (int nt = 0; nt < 8; nt++) {
            #pragma unroll
            for (int j = 0; j < 2; j++) {
                int kl = nt * 8 + 2 * lq + j;
                bool ok = (kt + kl < LL) && (msk[kl] > 0);
                if (!ok) { sacc[nt][j] = -1e30f; sacc[nt][2 + j] = -1e30f; }
                rmax0 = fmaxf(rmax0, sacc[nt][j]);
                rmax1 = fmaxf(rmax1, sacc[nt][2 + j]);
            }
        }
        #pragma unroll
        for (int o = 1; o <= 2; o <<= 1) {
            rmax0 = fmaxf(rmax0, __shfl_xor_sync(0xffffffffu, rmax0, o));
            rmax1 = fmaxf(rmax1, __shfl_xor_sync(0xffffffffu, rmax1, o));
        }

        float m0n = fmaxf(m0, rmax0);
        float m1n = fmaxf(m1, rmax1);
        float alpha0 = __expf(m0 - m0n);
        float alpha1 = __expf(m1 - m1n);
        m0 = m0n; m1 = m1n;

        float rs0 = 0.0f, rs1 = 0.0f;
        #pragma unroll
        for (int nt = 0; nt < 8; nt++) {
            #pragma unroll
            for (int j = 0; j < 2; j++) {
                float p0 = __expf(sacc[nt][j] - m0);
                float p1 = __expf(sacc[nt][2 + j] - m1);
                sacc[nt][j] = p0;     rs0 += p0;
                sacc[nt][2 + j] = p1; rs1 += p1;
            }
        }
        #pragma unroll
        for (int o = 1; o <= 2; o <<= 1) {
            rs0 += __shfl_xor_sync(0xffffffffu, rs0, o);
            rs1 += __shfl_xor_sync(0xffffffffu, rs1, o);
        }
        l0 = l0 * alpha0 + rs0;
        l1 = l1 * alpha1 + rs1;

        #pragma unroll
        for (int nt = 0; nt < 8; nt++) {
            oacc[nt][0] *= alpha0; oacc[nt][1] *= alpha0;
            oacc[nt][2] *= alpha1; oacc[nt][3] *= alpha1;
        }

        __syncthreads();

        #pragma unroll
        for (int nt = 0; nt < 8; nt++) {
            int c = nt * 8 + 2 * lq;
            KPs[(wr + lg)     * QS_STRIDE + c]     = f2tf32(sacc[nt][0]);
            KPs[(wr + lg)     * QS_STRIDE + c + 1] = f2tf32(sacc[nt][1]);
            KPs[(wr + lg + 8) * QS_STRIDE + c]     = f2tf32(sacc[nt][2]);
            KPs[(wr + lg + 8) * QS_STRIDE + c + 1] = f2tf32(sacc[nt][3]);
        }
        __syncwarp();

        #pragma unroll
        for (int ks = 0; ks < 8; ks++) {
            int kb = ks * 8;
            unsigned af[4];
            af[0] = KPs[(wr + lg)     * QS_STRIDE + kb + lq];
            af[1] = KPs[(wr + lg + 8) * QS_STRIDE + kb + lq];
            af[2] = KPs[(wr + lg)     * QS_STRIDE + kb + lq + 4];
            af[3] = KPs[(wr + lg + 8) * QS_STRIDE + kb + lq + 4];
            #pragma unroll
            for (int nt = 0; nt < 8; nt++) {
                unsigned bf[2];
                bf[0] = Vs[(kb + lq)     * VS_STRIDE + nt * 8 + lg];
                bf[1] = Vs[(kb + lq + 4) * VS_STRIDE + nt * 8 + lg];
                mma_tf32(oacc[nt], af, bf);
            }
        }
    }

    float inv0 = 1.0f / fmaxf(l0, 1e-30f);
    float inv1 = 1.0f / fmaxf(l1, 1e-30f);
    int r0 = q0 + wr + lg;
    int r1 = r0 + 8;
    #pragma unroll
    for (int nt = 0; nt < 8; nt++) {
        int c = nt * 8 + 2 * lq;
        if (r0 < LL)
            *(__half2*)&attout[((size_t)(b * LL + r0)) * HH + h * DHH + c] =
                __floats2half2_rn(oacc[nt][0] * inv0, oacc[nt][1] * inv0);
        if (r1 < LL)
            *(__half2*)&attout[((size_t)(b * LL + r1)) * HH + h * DHH + c] =
                __floats2half2_rn(oacc[nt][2] * inv1, oacc[nt][3] * inv1);
    }
}

// ---------------------------------------------------------------------------
// Launch
// ---------------------------------------------------------------------------
extern "C" void kernel_launch(void* const* d_in, const int* in_sizes, int n_in,
                              void* d_out, int out_size) {
    const float* x         = (const float*)d_in[0];
    const int*   mask      = (const int*)  d_in[1];
    const float* conv_ln_g = (const float*)d_in[2];
    const float* conv_ln_b = (const float*)d_in[3];
    const float* dw_w      = (const float*)d_in[4];
    const float* dw_b      = (const float*)d_in[5];
    const float* pw_w      = (const float*)d_in[6];
    const float* pw_b      = (const float*)d_in[7];
    const float* att_ln_g  = (const float*)d_in[8];
    const float* att_ln_b  = (const float*)d_in[9];
    const float* qkv_w     = (const float*)d_in[10];
    const float* qkv_b     = (const float*)d_in[11];
    const float* out_w     = (const float*)d_in[12];
    const float* out_b     = (const float*)d_in[13];
    const float* ff_ln_g   = (const float*)d_in[14];
    const float* ff_ln_b   = (const float*)d_in[15];
    const float* ff_w      = (const float*)d_in[16];
    const float* ff_b      = (const float*)d_in[17];
    float* out = (float*)d_out;

    __half *normh, *dwouth, *attouth, *wth;
    float *qkv;
    cudaGetSymbolAddress((void**)&normh,   g_norm_h);
    cudaGetSymbolAddress((void**)&dwouth,  g_dwout_h);
    cudaGetSymbolAddress((void**)&qkv,     g_qkv);
    cudaGetSymbolAddress((void**)&attouth, g_attout_h);
    cudaGetSymbolAddress((void**)&wth,     g_wth);

    cudaFuncSetAttribute(flash_kernel,
                         cudaFuncAttributeMaxDynamicSharedMemorySize, FLASH_SMEM);
    cudaFuncSetAttribute(gemm_f16_kernel<true, true, false>,
                         cudaFuncAttributeMaxDynamicSharedMemorySize, GEMM_SMEM);
    cudaFuncSetAttribute(gemm_f16_kernel<false, false, true>,
                         cudaFuncAttributeMaxDynamicSharedMemorySize, GEMM_SMEM);
    cudaFuncSetAttribute(gemm_f16_kernel<false, true, false>,
                         cudaFuncAttributeMaxDynamicSharedMemorySize, GEMM_SMEM);

    const int elems = MM * HH;

    // Pre-convert all GEMM weights to fp16 (one launch)
    conv_all_w_kernel<<<(WT_TOT / 4 + 255) / 256, 256>>>(pw_w, qkv_w, out_w, ff_w, wth);

    add_pe_kernel<<<(elems + 255) / 256, 256>>>(x, out);

    for (int i = 0; i < NCC; i++) {
        ln_dwconv_kernel<<<dim3(BB, LL / CTILE), 256>>>(
            out, dwouth, conv_ln_g + i * HH, conv_ln_b + i * HH,
            dw_w + i * HH * KW, dw_b + i * HH);
        gemm_f16_kernel<true, true, false><<<dim3(HH / 128, MM / 128), 256, GEMM_SMEM>>>(
            dwouth, wth + WT_PW + (size_t)i * HH * HH, pw_b + i * HH, out, out, MM, HH, HH);
    }

    ln_h_kernel<<<MM, 128>>>(out, normh, att_ln_g, att_ln_b);
    gemm_f16_kernel<false, false, true><<<dim3(H3 / 128, MM / 128), 256, GEMM_SMEM>>>(
        normh, wth + WT_QKV, qkv_b, nullptr, qkv, MM, H3, HH);

    flash_kernel<<<dim3(BB * NHH, (LL + 63) / 64), 128, FLASH_SMEM>>>(qkv, mask, attouth);

    gemm_f16_kernel<false, true, false><<<dim3(HH / 128, MM / 128), 256, GEMM_SMEM>>>(
        attouth, wth + WT_OUT, out_b, out, out, MM, HH, HH);

    ln_h_kernel<<<MM, 128>>>(out, normh, ff_ln_g, ff_ln_b);
    gemm_f16_kernel<true, true, false><<<dim3(HH / 128, MM / 128), 256, GEMM_SMEM>>>(
        normh, wth + WT_FF, ff_b, out, out, MM, HH, HH);
}

// round 12
// speedup vs baseline: 1.6467x; 1.0344x over previous
#include <cuda_runtime.h>
#include <cuda_fp16.h>
#include <math.h>
#include <stdint.h>

// Problem constants
#define BB   32
#define LL   400
#define HH   512
#define NHH  8
#define DHH  64
#define KW   7
#define NCC  4
#define MM   (BB * LL)      // 12800 tokens
#define H3   (3 * HH)       // 1536

// ---------------------------------------------------------------------------
// Scratch
// ---------------------------------------------------------------------------
__device__ __half g_norm_h [MM * HH];
__device__ __half g_dwout_h[MM * HH];
__device__ __half g_qkv_h  [MM * H3];
__device__ __half g_attout_h[MM * HH];
// fp16 weights: pw | qkv | out | ff
#define WT_PW   0
#define WT_QKV  (NCC * HH * HH)
#define WT_OUT  (WT_QKV + H3 * HH)
#define WT_FF   (WT_OUT + HH * HH)
#define WT_TOT  (WT_FF + HH * HH)
__device__ __half g_wth[WT_TOT];

// ---------------------------------------------------------------------------
// helpers
// ---------------------------------------------------------------------------
// fp16 mma, fp32 accumulate, m16n8k16
__device__ __forceinline__ void mma_f16(float* d, const unsigned* a, const unsigned* b) {
    asm volatile(
        "mma.sync.aligned.m16n8k16.row.col.f32.f16.f16.f32 "
        "{%0,%1,%2,%3}, {%4,%5,%6,%7}, {%8,%9}, {%0,%1,%2,%3};\n"
        : "+f"(d[0]), "+f"(d[1]), "+f"(d[2]), "+f"(d[3])
        : "r"(a[0]), "r"(a[1]), "r"(a[2]), "r"(a[3]), "r"(b[0]), "r"(b[1]));
}

__device__ __forceinline__ void cp_async16(void* smem_dst, const void* gsrc) {
    unsigned sa = (unsigned)__cvta_generic_to_shared(smem_dst);
    asm volatile("cp.async.cg.shared.global [%0], [%1], 16;\n" :: "r"(sa), "l"(gsrc));
}

// output-type-dispatched pair store
__device__ __forceinline__ void store2(float* p, float a, float b) {
    *(float2*)p = make_float2(a, b);
}
__device__ __forceinline__ void store2(__half* p, float a, float b) {
    *(__half2*)p = __floats2half2_rn(a, b);
}

// ---------------------------------------------------------------------------
// Weight pre-convert to fp16 (one launch).
// ---------------------------------------------------------------------------
__global__ void conv_all_w_kernel(const float* __restrict__ pw,
                                  const float* __restrict__ qkvw,
                                  const float* __restrict__ ow,
                                  const float* __restrict__ ffw,
                                  __half* __restrict__ out) {
    int i = blockIdx.x * blockDim.x + threadIdx.x;       // float4 index
    const int n_pw  = WT_QKV / 4;
    const int n_qkv = (WT_OUT - WT_QKV) / 4;
    const int n_o   = (WT_FF - WT_OUT) / 4;
    const int n_tot = WT_TOT / 4;
    if (i >= n_tot) return;
    const float* src; int off;
    if (i < n_pw)                     { src = pw;   off = i; }
    else if (i < n_pw + n_qkv)        { src = qkvw; off = i - n_pw; }
    else if (i < n_pw + n_qkv + n_o)  { src = ow;   off = i - n_pw - n_qkv; }
    else                              { src = ffw;  off = i - n_pw - n_qkv - n_o; }
    float4 v = ((const float4*)src)[off];
    ((__half2*)out)[i * 2]     = __floats2half2_rn(v.x, v.y);
    ((__half2*)out)[i * 2 + 1] = __floats2half2_rn(v.z, v.w);
}

// ---------------------------------------------------------------------------
// out = x + positional encoding
// ---------------------------------------------------------------------------
__global__ void add_pe_kernel(const float* __restrict__ x, float* __restrict__ out) {
    int idx = blockIdx.x * blockDim.x + threadIdx.x;
    if (idx >= MM * HH) return;
    int h = idx & (HH - 1);
    int l = (idx / HH) % LL;
    float freq = expf(-(float)(h & ~1) * (9.210340371976184f / (float)HH));
    float a = (float)l * freq;
    float pe = (h & 1) ? cosf(a) : sinf(a);
    out[idx] = x[idx] + pe;
}

// ---------------------------------------------------------------------------
// LayerNorm -> fp16 output (feeds GEMM A). One block/row, 128 thr.
// ---------------------------------------------------------------------------
__global__ void ln_h_kernel(const float* __restrict__ in, __half* __restrict__ out,
                            const float* __restrict__ gw, const float* __restrict__ gb) {
    int row = blockIdx.x;
    int t   = threadIdx.x;  // 128
    const float4* p = (const float4*)(in + (size_t)row * HH);
    float4 v = p[t];

    __shared__ float sh[4];

    float s = v.x + v.y + v.z + v.w;
    #pragma unroll
    for (int o = 16; o > 0; o >>= 1) s += __shfl_down_sync(0xffffffffu, s, o);
    if ((t & 31) == 0) sh[t >> 5] = s;
    __syncthreads();
    float mean = (sh[0] + sh[1] + sh[2] + sh[3]) * (1.0f / HH);
    __syncthreads();

    float dx = v.x - mean, dy = v.y - mean, dz = v.z - mean, dw = v.w - mean;
    float q = dx * dx + dy * dy + dz * dz + dw * dw;
    #pragma unroll
    for (int o = 16; o > 0; o >>= 1) q += __shfl_down_sync(0xffffffffu, q, o);
    if ((t & 31) == 0) sh[t >> 5] = q;
    __syncthreads();
    float var  = (sh[0] + sh[1] + sh[2] + sh[3]) * (1.0f / HH);
    float rstd = rsqrtf(var + 1e-5f);

    float4 g4 = ((const float4*)gw)[t];
    float4 b4 = ((const float4*)gb)[t];
    float ox = dx * rstd * g4.x + b4.x;
    float oy = dy * rstd * g4.y + b4.y;
    float oz = dz * rstd * g4.z + b4.z;
    float ow = dw * rstd * g4.w + b4.w;
    __half2* o2 = (__half2*)(out + (size_t)row * HH);
    o2[t * 2]     = __floats2half2_rn(ox, oy);
    o2[t * 2 + 1] = __floats2half2_rn(oz, ow);
}

// ---------------------------------------------------------------------------
// Fused LayerNorm + depthwise conv (K=7, pad 3) -> fp16 output.
// ---------------------------------------------------------------------------
#define CTILE 16
#define CHALO 3
#define CROWS (CTILE + 2 * CHALO)   // 22

__global__ void __launch_bounds__(256)
ln_dwconv_kernel(const float* __restrict__ in, __half* __restrict__ dwout,
                 const float* __restrict__ gw, const float* __restrict__ gb,
                 const float* __restrict__ w, const float* __restrict__ bias) {
    __shared__ float sm[CROWS * HH];

    int b    = blockIdx.x;
    int t0   = blockIdx.y * CTILE;
    int tid  = threadIdx.x;
    int warp = tid >> 5;
    int lane = tid & 31;

    for (int rr = warp; rr < CROWS; rr += 8) {
        int l = t0 - CHALO + rr;
        if (l < 0 || l >= LL) {
            #pragma unroll
            for (int j = 0; j < 4; j++)
                *(float4*)&sm[rr * HH + lane * 4 + j * 128] = make_float4(0.f, 0.f, 0.f, 0.f);
            continue;
        }
        const float4* p = (const float4*)(in + ((size_t)(b * LL + l)) * HH);
        float4 v[4];
        float s = 0.0f;
        #pragma unroll
        for (int j = 0; j < 4; j++) {
            v[j] = p[lane + j * 32];
            s += v[j].x + v[j].y + v[j].z + v[j].w;
        }
        #pragma unroll
        for (int o = 16; o > 0; o >>= 1) s += __shfl_xor_sync(0xffffffffu, s, o);
        float mean = s * (1.0f / HH);

        float q = 0.0f;
        #pragma unroll
        for (int j = 0; j < 4; j++) {
            float dx = v[j].x - mean, dy = v[j].y - mean;
            float dz = v[j].z - mean, dw = v[j].w - mean;
            q += dx * dx + dy * dy + dz * dz + dw * dw;
        }
        #pragma unroll
        for (int o = 16; o > 0; o >>= 1) q += __shfl_xor_sync(0xffffffffu, q, o);
        float rstd = rsqrtf(q * (1.0f / HH) + 1e-5f);

        #pragma unroll
        for (int j = 0; j < 4; j++) {
            int c = lane * 4 + j * 128;
            float4 g4 = *(const float4*)&gw[c];
            float4 b4 = *(const float4*)&gb[c];
            float4 o4;
            o4.x = (v[j].x - mean) * rstd * g4.x + b4.x;
            o4.y = (v[j].y - mean) * rstd * g4.y + b4.y;
            o4.z = (v[j].z - mean) * rstd * g4.z + b4.z;
            o4.w = (v[j].w - mean) * rstd * g4.w + b4.w;
            *(float4*)&sm[rr * HH + c] = o4;
        }
    }
    __syncthreads();

    int c0 = tid * 2;
    float wr0[KW], wr1[KW];
    #pragma unroll
    for (int k = 0; k < KW; k++) {
        wr0[k] = w[c0 * KW + k];
        wr1[k] = w[(c0 + 1) * KW + k];
    }
    float bi0 = bias[c0], bi1 = bias[c0 + 1];

    #pragma unroll 4
    for (int r = 0; r < CTILE; r++) {
        float a0 = bi0, a1 = bi1;
        #pragma unroll
        for (int k = 0; k < KW; k++) {
            float2 x = *(const float2*)&sm[(r + k) * HH + c0];
            a0 += x.x * wr0[k];
            a1 += x.y * wr1[k];
        }
        *(__half2*)&dwout[((size_t)(b * LL + t0 + r)) * HH + c0] =
            __floats2half2_rn(a0, a1);
    }
}

// ---------------------------------------------------------------------------
// fp16 tensor-core GEMM (BM=128, BN=128, BK=32 halves, 3-stage cp.async).
// ---------------------------------------------------------------------------
#define GH_ROWW  20
#define GH_SS    (128 * GH_ROWW)
#define GH_NSTG  3
#define GEMM_SMEM (GH_NSTG * GH_SS * 2 * 4)         // 61440 bytes

template <bool RELU, bool RES, typename TOUT>
__global__ void __launch_bounds__(256, 2)
gemm_f16_kernel(const __half* __restrict__ A, const __half* __restrict__ W,
                const float* __restrict__ bias, const float* __restrict__ R,
                TOUT* __restrict__ C, int Md, int Nd, int Kd) {
    extern __shared__ unsigned gsm[];
    unsigned* Asm = gsm;
    unsigned* Bsm = gsm + GH_NSTG * GH_SS;

    int tid  = threadIdx.x;
    int m0   = blockIdx.y * 128;
    int n0   = blockIdx.x * 128;
    int warp = tid >> 5;
    int lane = tid & 31;
    int wm   = (warp >> 2) * 64;
    int wn   = (warp & 3) * 32;
    int lg   = lane >> 2;
    int lq   = lane & 3;

    int lrow = tid >> 2;
    int lchunk = (tid & 3);
    int sw = lrow * GH_ROWW + lchunk * 4;
    int sw2 = (64 + lrow) * GH_ROWW + lchunk * 4;

    const __half* Ag0 = &A[(size_t)(m0 + lrow)      * Kd + lchunk * 8];
    const __half* Ag1 = &A[(size_t)(m0 + 64 + lrow) * Kd + lchunk * 8];
    const __half* Wg0 = &W[(size_t)(n0 + lrow)      * Kd + lchunk * 8];
    const __half* Wg1 = &W[(size_t)(n0 + 64 + lrow) * Kd + lchunk * 8];

    float acc[4][4][4];
    #pragma unroll
    for (int i = 0; i < 4; i++)
        #pragma unroll
        for (int j = 0; j < 4; j++)
            #pragma unroll
            for (int r = 0; r < 4; r++) acc[i][j][r] = 0.0f;

    #define LOAD_STAGE(s, ko)                                                   \
    {                                                                           \
        unsigned* As_ = Asm + (s) * GH_SS;                                      \
        unsigned* Bs_ = Bsm + (s) * GH_SS;                                      \
        cp_async16(As_ + sw,  Ag0 + (ko));                                      \
        cp_async16(As_ + sw2, Ag1 + (ko));                                      \
        cp_async16(Bs_ + sw,  Wg0 + (ko));                                      \
        cp_async16(Bs_ + sw2, Wg1 + (ko));                                      \
        asm volatile("cp.async.commit_group;\n");                               \
    }

    int nit = Kd >> 5;
    LOAD_STAGE(0, 0);
    if (nit > 1) LOAD_STAGE(1, 32);

    for (int it = 0; it < nit; it++) {
        if (it + 1 < nit)
            asm volatile("cp.async.wait_group 1;\n");
        else
            asm volatile("cp.async.wait_group 0;\n");
        __syncthreads();
        if (it + 2 < nit) LOAD_STAGE((it + 2) % GH_NSTG, (it + 2) << 5);

        int cur = it % GH_NSTG;
        const unsigned* Asc = Asm + cur * GH_SS;
        const unsigned* Bsc = Bsm + cur * GH_SS;

        #pragma unroll
        for (int ks = 0; ks < 2; ks++) {
            int kb = ks * 8;
            unsigned af[4][4], bf[4][2];
            #pragma unroll
            for (int mt = 0; mt < 4; mt++) {
                int mr = wm + mt * 16 + lg;
                af[mt][0] = Asc[mr * GH_ROWW + kb + lq];
                af[mt][1] = Asc[(mr + 8) * GH_ROWW + kb + lq];
                af[mt][2] = Asc[mr * GH_ROWW + kb + lq + 4];
                af[mt][3] = Asc[(mr + 8) * GH_ROWW + kb + lq + 4];
            }
            #pragma unroll
            for (int nt = 0; nt < 4; nt++) {
                int nr = wn + nt * 8 + lg;
                bf[nt][0] = Bsc[nr * GH_ROWW + kb + lq];
                bf[nt][1] = Bsc[nr * GH_ROWW + kb + lq + 4];
            }
            #pragma unroll
            for (int mt = 0; mt < 4; mt++)
                #pragma unroll
                for (int nt = 0; nt < 4; nt++)
                    mma_f16(acc[mt][nt], af[mt], bf[nt]);
        }
    }
    #undef LOAD_STAGE

    #pragma unroll
    for (int mt = 0; mt < 4; mt++) {
        #pragma unroll
        for (int half = 0; half < 2; half++) {
            int m = m0 + wm + mt * 16 + lg + half * 8;
            #pragma unroll
            for (int nt = 0; nt < 4; nt++) {
                int n = n0 + wn + nt * 8 + 2 * lq;
                float v0 = acc[mt][nt][half * 2 + 0] + bias[n];
                float v1 = acc[mt][nt][half * 2 + 1] + bias[n + 1];
                if (RELU) { v0 = fmaxf(v0, 0.0f); v1 = fmaxf(v1, 0.0f); }
                if (RES)  { v0 += R[(size_t)m * Nd + n]; v1 += R[(size_t)m * Nd + n + 1]; }
                store2(&C[(size_t)m * Nd + n], v0, v1);
            }
        }
    }
}

// ---------------------------------------------------------------------------
// Fused flash attention, fp16 MMA (m16n8k16), online softmax.
// Smem: Qs[64][36]w, KPs[64][36]w (K, reused for P), Vst[64][36]w (V^T [d][key]).
// ---------------------------------------------------------------------------
#define FW 36   // words per smem row

__global__ void __launch_bounds__(128)
flash_kernel(const __half* __restrict__ qkv, const int* __restrict__ mask,
             __half* __restrict__ attout) {
    __shared__ unsigned Qs [64 * FW];
    __shared__ unsigned KPs[64 * FW];
    __shared__ unsigned Vst[64 * FW];
    __shared__ int msk[64];

    int bh = blockIdx.x;
    int b  = bh >> 3;
    int h  = bh & 7;
    int q0 = blockIdx.y * 64;

    int tid  = threadIdx.x;
    int warp = tid >> 5;
    int lane = tid & 31;
    int wr   = warp * 16;
    int lg   = lane >> 2;
    int lq   = lane & 3;

    const __half2 qsc = __float2half2_rn(0.125f);

    // Q load: 64 rows x 64 halves = 64 x 8 uint4 chunks (512 total)
    for (int i = tid; i < 512; i += 128) {
        int r  = i >> 3;
        int cw = (i & 7) * 4;            // word offset 0..28
        int qr = q0 + r; if (qr > LL - 1) qr = LL - 1;
        uint4 v = *(const uint4*)&qkv[((size_t)(b * LL + qr)) * H3 + h * DHH + cw * 2];
        __half2 h0 = __hmul2(*(__half2*)&v.x, qsc);
        __half2 h1 = __hmul2(*(__half2*)&v.y, qsc);
        __half2 h2 = __hmul2(*(__half2*)&v.z, qsc);
        __half2 h3 = __hmul2(*(__half2*)&v.w, qsc);
        uint4 sv;
        sv.x = *(unsigned*)&h0; sv.y = *(unsigned*)&h1;
        sv.z = *(unsigned*)&h2; sv.w = *(unsigned*)&h3;
        *(uint4*)&Qs[r * FW + cw] = sv;
    }

    float oacc[8][4];
    #pragma unroll
    for (int nt = 0; nt < 8; nt++)
        #pragma unroll
        for (int r2 = 0; r2 < 4; r2++) oacc[nt][r2] = 0.0f;
    float m0 = -1e30f, m1 = -1e30f, l0 = 0.0f, l1 = 0.0f;

    for (int kt = 0; kt < LL; kt += 64) {
        __syncthreads();

        // K tile -> KPs [key][d]; V tile transposed -> Vst [d][key]
        for (int i = tid; i < 512; i += 128) {
            int r  = i >> 3;
            int cw = (i & 7) * 4;
            int kr = kt + r; if (kr > LL - 1) kr = LL - 1;
            const __half* base = &qkv[((size_t)(b * LL + kr)) * H3 + h * DHH + cw * 2];
            uint4 kv = *(const uint4*)(base + HH);
            *(uint4*)&KPs[r * FW + cw] = kv;
            uint4 vv = *(const uint4*)(base + 2 * HH);
            const __half* vh = (const __half*)&vv;
            __half* Vh = (__half*)Vst;
            #pragma unroll
            for (int j = 0; j < 8; j++)
                Vh[(cw * 2 + j) * (FW * 2) + r] = vh[j];
        }
        if (tid < 64) msk[tid] = (kt + tid < LL) ? mask[b * LL + kt + tid] : 0;
        __syncthreads();

        // S = Q @ K^T
        float sacc[8][4];
        #pragma unroll
        for (int nt = 0; nt < 8; nt++)
            #pragma unroll
            for (int r2 = 0; r2 < 4; r2++) sacc[nt][r2] = 0.0f;

        #pragma unroll
        for (int ks = 0; ks < 4; ks++) {
            int kb = ks * 8;
            unsigned af[4];
            af[0] = Qs[(wr + lg)     * FW + kb + lq];
            af[1] = Qs[(wr + lg + 8) * FW + kb + lq];
            af[2] = Qs[(wr + lg)     * FW + kb + lq + 4];
            af[3] = Qs[(wr + lg + 8) * FW + kb + lq + 4];
            #pragma unroll
            for (int nt = 0; nt < 8; nt++) {
                unsigned bf[2];
                bf[0] = KPs[(nt * 8 + lg) * FW + kb + lq];
                bf[1] = KPs[(nt * 8 + lg) * FW + kb + lq + 4];
                mma_f16(sacc[nt], af, bf);
            }
        }

        // Mask + row max
        float rmax0 = -1e30f, rmax1 = -1e30f;
        #pragma unroll
        for (int nt = 0; nt < 8; nt++) {
            #pragma unroll
            for (int j = 0; j < 2; j++) {
                int kl = nt * 8 + 2 * lq + j;
                bool ok = (kt + kl < LL) && (msk[kl] > 0);
                if (!ok) { sacc[nt][j] = -1e30f; sacc[nt][2 + j] = -1e30f; }
                rmax0 = fmaxf(rmax0, sacc[nt][j]);
                rmax1 = fmaxf(rmax1, sacc[nt][2 + j]);
            }
        }
        #pragma unroll
        for (int o = 1; o <= 2; o <<= 1) {
            rmax0 = fmaxf(rmax0, __shfl_xor_sync(0xffffffffu, rmax0, o));
            rmax1 = fmaxf(rmax1, __shfl_xor_sync(0xffffffffu, rmax1, o));
        }

        float m0n = fmaxf(m0, rmax0);
        float m1n = fmaxf(m1, rmax1);
        float alpha0 = __expf(m0 - m0n);
        float alpha1 = __expf(m1 - m1n);
        m0 = m0n; m1 = m1n;

        float rs0 = 0.0f, rs1 = 0.0f;
        #pragma unroll
        for (int nt = 0; nt < 8; nt++) {
            #pragma unroll
            for (int j = 0; j < 2; j++) {
                float p0 = __expf(sacc[nt][j] - m0);
                float p1 = __expf(sacc[nt][2 + j] - m1);
                sacc[nt][j] = p0;     rs0 += p0;
                sacc[nt][2 + j] = p1; rs1 += p1;
            }
        }
        #pragma unroll
        for (int o = 1; o <= 2; o <<= 1) {
            rs0 += __shfl_xor_sync(0xffffffffu, rs0, o);
            rs1 += __shfl_xor_sync(0xffffffffu, rs1, o);
        }
        l0 = l0 * alpha0 + rs0;
        l1 = l1 * alpha1 + rs1;

        #pragma unroll
        for (int nt = 0; nt < 8; nt++) {
            oacc[nt][0] *= alpha0; oacc[nt][1] *= alpha0;
            oacc[nt][2] *= alpha1; oacc[nt][3] *= alpha1;
        }

        // All warps done reading K before P overwrites it
        __syncthreads();

        // P (fp16) into KPs rows owned by this warp
        #pragma unroll
        for (int nt = 0; nt < 8; nt++) {
            __half2 p01 = __floats2half2_rn(sacc[nt][0], sacc[nt][1]);
            __half2 p23 = __floats2half2_rn(sacc[nt][2], sacc[nt][3]);
            KPs[(wr + lg)     * FW + nt * 4 + lq] = *(unsigned*)&p01;
            KPs[(wr + lg + 8) * FW + nt * 4 + lq] = *(unsigned*)&p23;
        }
        __syncwarp();

        // O += P @ V  (A = P [q][key], B = Vst [d][key])
        #pragma unroll
        for (int ks = 0; ks < 4; ks++) {
            int kb = ks * 8;
            unsigned af[4];
            af[0] = KPs[(wr + lg)     * FW + kb + lq];
            af[1] = KPs[(wr + lg + 8) * FW + kb + lq];
            af[2] = KPs[(wr + lg)     * FW + kb + lq + 4];
            af[3] = KPs[(wr + lg + 8) * FW + kb + lq + 4];
            #pragma unroll
            for (int nt = 0; nt < 8; nt++) {
                unsigned bf[2];
                bf[0] = Vst[(nt * 8 + lg) * FW + kb + lq];
                bf[1] = Vst[(nt * 8 + lg) * FW + kb + lq + 4];
                mma_f16(oacc[nt], af, bf);
            }
        }
    }

    float inv0 = 1.0f / fmaxf(l0, 1e-30f);
    float inv1 = 1.0f / fmaxf(l1, 1e-30f);
    int r0 = q0 + wr + lg;
    int r1 = r0 + 8;
    #pragma unroll
    for (int nt = 0; nt < 8; nt++) {
        int c = nt * 8 + 2 * lq;
        if (r0 < LL)
            *(__half2*)&attout[((size_t)(b * LL + r0)) * HH + h * DHH + c] =
                __floats2half2_rn(oacc[nt][0] * inv0, oacc[nt][1] * inv0);
        if (r1 < LL)
            *(__half2*)&attout[((size_t)(b * LL + r1)) * HH + h * DHH + c] =
                __floats2half2_rn(oacc[nt][2] * inv1, oacc[nt][3] * inv1);
    }
}

// ---------------------------------------------------------------------------
// Launch
// ---------------------------------------------------------------------------
extern "C" void kernel_launch(void* const* d_in, const int* in_sizes, int n_in,
                              void* d_out, int out_size) {
    const float* x         = (const float*)d_in[0];
    const int*   mask      = (const int*)  d_in[1];
    const float* conv_ln_g = (const float*)d_in[2];
    const float* conv_ln_b = (const float*)d_in[3];
    const float* dw_w      = (const float*)d_in[4];
    const float* dw_b      = (const float*)d_in[5];
    const float* pw_w      = (const float*)d_in[6];
    const float* pw_b      = (const float*)d_in[7];
    const float* att_ln_g  = (const float*)d_in[8];
    const float* att_ln_b  = (const float*)d_in[9];
    const float* qkv_w     = (const float*)d_in[10];
    const float* qkv_b     = (const float*)d_in[11];
    const float* out_w     = (const float*)d_in[12];
    const float* out_b     = (const float*)d_in[13];
    const float* ff_ln_g   = (const float*)d_in[14];
    const float* ff_ln_b   = (const float*)d_in[15];
    const float* ff_w      = (const float*)d_in[16];
    const float* ff_b      = (const float*)d_in[17];
    float* out = (float*)d_out;

    __half *normh, *dwouth, *qkvh, *attouth, *wth;
    cudaGetSymbolAddress((void**)&normh,   g_norm_h);
    cudaGetSymbolAddress((void**)&dwouth,  g_dwout_h);
    cudaGetSymbolAddress((void**)&qkvh,    g_qkv_h);
    cudaGetSymbolAddress((void**)&attouth, g_attout_h);
    cudaGetSymbolAddress((void**)&wth,     g_wth);

    cudaFuncSetAttribute(gemm_f16_kernel<true, true, float>,
                         cudaFuncAttributeMaxDynamicSharedMemorySize, GEMM_SMEM);
    cudaFuncSetAttribute(gemm_f16_kernel<false, false, __half>,
                         cudaFuncAttributeMaxDynamicSharedMemorySize, GEMM_SMEM);
    cudaFuncSetAttribute(gemm_f16_kernel<false, true, float>,
                         cudaFuncAttributeMaxDynamicSharedMemorySize, GEMM_SMEM);

    const int elems = MM * HH;

    conv_all_w_kernel<<<(WT_TOT / 4 + 255) / 256, 256>>>(pw_w, qkv_w, out_w, ff_w, wth);

    add_pe_kernel<<<(elems + 255) / 256, 256>>>(x, out);

    for (int i = 0; i < NCC; i++) {
        ln_dwconv_kernel<<<dim3(BB, LL / CTILE), 256>>>(
            out, dwouth, conv_ln_g + i * HH, conv_ln_b + i * HH,
            dw_w + i * HH * KW, dw_b + i * HH);
        gemm_f16_kernel<true, true, float><<<dim3(HH / 128, MM / 128), 256, GEMM_SMEM>>>(
            dwouth, wth + WT_PW + (size_t)i * HH * HH, pw_b + i * HH, out, out, MM, HH, HH);
    }

    ln_h_kernel<<<MM, 128>>>(out, normh, att_ln_g, att_ln_b);
    gemm_f16_kernel<false, false, __half><<<dim3(H3 / 128, MM / 128), 256, GEMM_SMEM>>>(
        normh, wth + WT_QKV, qkv_b, (const float*)nullptr, qkvh, MM, H3, HH);

    flash_kernel<<<dim3(BB * NHH, (LL + 63) / 64), 128>>>(qkvh, mask, attouth);

    gemm_f16_kernel<false, true, float><<<dim3(HH / 128, MM / 128), 256, GEMM_SMEM>>>(
        attouth, wth + WT_OUT, out_b, out, out, MM, HH, HH);

    ln_h_kernel<<<MM, 128>>>(out, normh, ff_ln_g, ff_ln_b);
    gemm_f16_kernel<true, true, float><<<dim3(HH / 128, MM / 128), 256, GEMM_SMEM>>>(
        normh, wth + WT_FF, ff_b, out, out, MM, HH, HH);
}